// round 7
// baseline (speedup 1.0000x reference)
#include <cuda_runtime.h>
#include <math.h>
#include <stdint.h>

#define N_TOK 8192
#define DM    1024
#define DFF   4096
#define NE    8
#define TOPK  2
#define CAP   1280
#define SROWB 80          // smem row stride bytes (64 data + 16 pad, conflict-free)
#define SSTAGE 40960      // bytes per pipeline stage

// ---------------- scratch ----------------
__device__ float    g_h  [2 * NE * CAP * DFF];          // gemm13 fp32 out
__device__ float    g_ob [2 * NE * CAP * DM];           // gemm2 fp32 out
__device__ uint32_t g_ah [2 * NE * CAP * DM / 4];       // x int8 hi (packed)
__device__ uint32_t g_al [2 * NE * CAP * DM / 4];       // x int8 lo
__device__ float    g_sa [2 * NE * CAP];                // x row scales
__device__ uint32_t g_hh [2 * NE * CAP * DFF / 4];      // h int8 hi
__device__ uint32_t g_hl [2 * NE * CAP * DFF / 4];      // h int8 lo
__device__ float    g_sh [2 * NE * CAP];                // h row scales
__device__ uint32_t g_w1h[NE * DFF * DM / 4];
__device__ uint32_t g_w1l[NE * DFF * DM / 4];
__device__ uint32_t g_w3h[NE * DFF * DM / 4];
__device__ uint32_t g_w3l[NE * DFF * DM / 4];
__device__ uint32_t g_w2h[NE * DM * DFF / 4];
__device__ uint32_t g_w2l[NE * DM * DFF / 4];
__device__ float    g_s1 [NE * DFF];
__device__ float    g_s3 [NE * DFF];
__device__ float    g_s2 [NE * DM];
__device__ float    g_probs[N_TOK * NE];
__device__ int      g_top_idx[N_TOK * TOPK];
__device__ float    g_top_w [N_TOK * TOPK];
__device__ int      g_pos   [N_TOK * TOPK];
__device__ int      g_cnt   [TOPK * NE];

// ---------------- helpers ----------------
__device__ __forceinline__ uint32_t smem_u32(const void* p) {
    uint32_t a;
    asm("{ .reg .u64 t; cvta.to.shared.u64 t, %1; cvt.u32.u64 %0, t; }" : "=r"(a) : "l"(p));
    return a;
}
__device__ __forceinline__ void mma_s8(int* c, const uint32_t* a, uint32_t b0, uint32_t b1) {
    asm volatile(
        "mma.sync.aligned.m16n8k32.row.col.s32.s8.s8.s32 "
        "{%0,%1,%2,%3}, {%4,%5,%6,%7}, {%8,%9}, {%0,%1,%2,%3};"
        : "+r"(c[0]), "+r"(c[1]), "+r"(c[2]), "+r"(c[3])
        : "r"(a[0]), "r"(a[1]), "r"(a[2]), "r"(a[3]), "r"(b0), "r"(b1));
}
__device__ __forceinline__ void cp16(uint32_t s, const void* g) {
    asm volatile("cp.async.cg.shared.global [%0], [%1], 16;" :: "r"(s), "l"(g) : "memory");
}
#define CP_COMMIT() asm volatile("cp.async.commit_group;" ::: "memory")
#define CP_WAIT1()  asm volatile("cp.async.wait_group 1;" ::: "memory")

__device__ __forceinline__ uint32_t pk4(int a, int b, int c, int d) {
    return (uint32_t)(a & 255) | ((uint32_t)(b & 255) << 8) |
           ((uint32_t)(c & 255) << 16) | ((uint32_t)(d & 255) << 24);
}
__device__ __forceinline__ int rni(float x) { return __float2int_rn(x); }

// ---------------- 0. per-row 2-level int8 quantization ----------------
// one block per row; K in {1024, 4096}. If segcnt: skip rows >= count (seg=CAP).
__global__ __launch_bounds__(256) void qrow_kernel(const float* __restrict__ src,
        uint32_t* __restrict__ dh, uint32_t* __restrict__ dl, float* __restrict__ sc,
        int K, int seg, const int* __restrict__ segcnt) {
    int row = blockIdx.x;
    if (segcnt) {
        int z = row / seg, m = row - z * seg;
        int cnt = segcnt[z]; if (cnt > seg) cnt = seg;
        if (m >= cnt) return;
    }
    int tid = threadIdx.x;
    int nj = K >> 10;
    const float4* s4 = (const float4*)(src + (size_t)row * K);
    float4 buf[4];
    float mx = 0.f;
    for (int j = 0; j < nj; j++) {
        float4 v = s4[j * 256 + tid]; buf[j] = v;
        mx = fmaxf(mx, fmaxf(fmaxf(fabsf(v.x), fabsf(v.y)), fmaxf(fabsf(v.z), fabsf(v.w))));
    }
    __shared__ float red[256];
    red[tid] = mx; __syncthreads();
    for (int s = 128; s > 0; s >>= 1) {
        if (tid < s) red[tid] = fmaxf(red[tid], red[tid + s]);
        __syncthreads();
    }
    float m0 = red[0];
    float inv = m0 > 0.f ? 127.f / m0 : 0.f;
    float s  = m0 * (1.f / 127.f);
    float rs = 127.f * inv;
    uint32_t* dhr = dh + (size_t)row * (K / 4);
    uint32_t* dlr = dl + (size_t)row * (K / 4);
    for (int j = 0; j < nj; j++) {
        float4 v = buf[j];
        int q0 = rni(v.x * inv), q1 = rni(v.y * inv), q2 = rni(v.z * inv), q3 = rni(v.w * inv);
        int l0 = rni((v.x - s * (float)q0) * rs);
        int l1 = rni((v.y - s * (float)q1) * rs);
        int l2 = rni((v.z - s * (float)q2) * rs);
        int l3 = rni((v.w - s * (float)q3) * rs);
        dhr[j * 256 + tid] = pk4(q0, q1, q2, q3);
        dlr[j * 256 + tid] = pk4(l0, l1, l2, l3);
    }
    if (tid == 0) sc[row] = s;
}

// ---------------- 1. router ----------------
__global__ __launch_bounds__(256) void router_kernel(const float* __restrict__ x,
                                                     const float* __restrict__ gw) {
    int warp = (blockIdx.x * blockDim.x + threadIdx.x) >> 5;
    int lane = threadIdx.x & 31;
    if (warp >= N_TOK) return;
    const float* xr = x + (size_t)warp * DM;
    float acc[NE];
#pragma unroll
    for (int e = 0; e < NE; e++) acc[e] = 0.f;
    for (int i = lane; i < DM; i += 32) {
        float xv = xr[i];
#pragma unroll
        for (int e = 0; e < NE; e++) acc[e] += xv * gw[e * DM + i];
    }
#pragma unroll
    for (int off = 16; off > 0; off >>= 1)
#pragma unroll
        for (int e = 0; e < NE; e++) acc[e] += __shfl_xor_sync(0xffffffffu, acc[e], off);
    if (lane == 0) {
        float mx = acc[0];
#pragma unroll
        for (int e = 1; e < NE; e++) mx = fmaxf(mx, acc[e]);
        float p[NE], s = 0.f;
#pragma unroll
        for (int e = 0; e < NE; e++) { p[e] = expf(acc[e] - mx); s += p[e]; }
        float inv = 1.f / s;
        int i0 = 0;
#pragma unroll
        for (int e = 1; e < NE; e++) if (p[e] > p[i0]) i0 = e;
        int i1 = (i0 == 0) ? 1 : 0;
#pragma unroll
        for (int e = 0; e < NE; e++) if (e != i0 && e != i1 && p[e] > p[i1]) i1 = e;
#pragma unroll
        for (int e = 0; e < NE; e++) g_probs[warp * NE + e] = p[e] * inv;
        float p0 = p[i0] * inv, p1 = p[i1] * inv;
        float ws = p0 + p1 + 1e-10f;
        g_top_idx[warp * 2 + 0] = i0;  g_top_w[warp * 2 + 0] = p0 / ws;
        g_top_idx[warp * 2 + 1] = i1;  g_top_w[warp * 2 + 1] = p1 / ws;
    }
}

// ---------------- 2. capacity scan ----------------
__global__ __launch_bounds__(256) void scan_kernel() {
    int k = blockIdx.x;
    int t = threadIdx.x;
    const int CH = N_TOK / 256;
    __shared__ int cnt[256][NE];
    int local[NE];
#pragma unroll
    for (int e = 0; e < NE; e++) local[e] = 0;
    for (int i = 0; i < CH; i++) local[g_top_idx[(t * CH + i) * 2 + k]]++;
#pragma unroll
    for (int e = 0; e < NE; e++) cnt[t][e] = local[e];
    __syncthreads();
    if (t < NE) {
        int run = 0;
        for (int i = 0; i < 256; i++) { int v = cnt[i][t]; cnt[i][t] = run; run += v; }
        g_cnt[k * NE + t] = run;
    }
    __syncthreads();
    int off[NE];
#pragma unroll
    for (int e = 0; e < NE; e++) off[e] = cnt[t][e];
    for (int i = 0; i < CH; i++) {
        int tk = (t * CH + i) * 2 + k;
        g_pos[tk] = off[g_top_idx[tk]]++;
    }
}

// ---------------- 3. gather + quantize x rows ----------------
__global__ __launch_bounds__(256) void gather_quant(const float* __restrict__ x) {
    int tk = blockIdx.x;
    int pos = g_pos[tk];
    if (pos >= CAP) return;
    int e = g_top_idx[tk];
    int k = tk & 1, t = tk >> 1;
    int tid = threadIdx.x;
    float4 v = ((const float4*)(x + (size_t)t * DM))[tid];
    float mx = fmaxf(fmaxf(fabsf(v.x), fabsf(v.y)), fmaxf(fabsf(v.z), fabsf(v.w)));
    __shared__ float red[256];
    red[tid] = mx; __syncthreads();
    for (int s = 128; s > 0; s >>= 1) {
        if (tid < s) red[tid] = fmaxf(red[tid], red[tid + s]);
        __syncthreads();
    }
    float m0 = red[0];
    float inv = m0 > 0.f ? 127.f / m0 : 0.f;
    float s  = m0 * (1.f / 127.f);
    float rs = 127.f * inv;
    int q0 = rni(v.x * inv), q1 = rni(v.y * inv), q2 = rni(v.z * inv), q3 = rni(v.w * inv);
    int l0 = rni((v.x - s * (float)q0) * rs);
    int l1 = rni((v.y - s * (float)q1) * rs);
    int l2 = rni((v.z - s * (float)q2) * rs);
    int l3 = rni((v.w - s * (float)q3) * rs);
    size_t rbase = ((size_t)(k * NE + e) * CAP + pos) * (DM / 4);
    g_ah[rbase + tid] = pk4(q0, q1, q2, q3);
    g_al[rbase + tid] = pk4(l0, l1, l2, l3);
    if (tid == 0) g_sa[(k * NE + e) * CAP + pos] = s;
}

// ---------------- 4. gemm13 int8: block 128M x 64N (x2 mats), warp 32x32, 3-stage ----------------
__global__ __launch_bounds__(256) void gemm13_i8() {
    int z = blockIdx.z, e = z & (NE - 1);
    int rows = g_cnt[z]; if (rows > CAP) rows = CAP;
    int m0 = blockIdx.y * 128; if (m0 >= rows) return;
    int n0 = blockIdx.x * 64;

    extern __shared__ char dsm[];
    uint32_t sb = smem_u32(dsm);

    const char* gAh = (const char*)g_ah  + (size_t)z * CAP * DM + (size_t)m0 * DM;
    const char* gAl = (const char*)g_al  + (size_t)z * CAP * DM + (size_t)m0 * DM;
    const char* gB1h = (const char*)g_w1h + (size_t)e * DFF * DM + (size_t)n0 * DM;
    const char* gB1l = (const char*)g_w1l + (size_t)e * DFF * DM + (size_t)n0 * DM;
    const char* gB3h = (const char*)g_w3h + (size_t)e * DFF * DM + (size_t)n0 * DM;
    const char* gB3l = (const char*)g_w3l + (size_t)e * DFF * DM + (size_t)n0 * DM;

    int tid = threadIdx.x, wid = tid >> 5, lane = tid & 31;
    int wm = wid >> 1, wn = wid & 1;             // 4m x 2n warps
    int g = lane >> 2, tg = lane & 3;

    auto issue = [&](int c) {
        uint32_t st = sb + (uint32_t)(c % 3) * SSTAGE;
        int k0 = c * 64;
#pragma unroll
        for (int i = 0; i < 2; i++) {            // A: 128 rows x 64B, 2 planes
            int f = tid + i * 256, r = f >> 2, c4 = f & 3;
            cp16(st + r * SROWB + c4 * 16,          gAh + (size_t)r * DM + k0 + c4 * 16);
            cp16(st + 10240u + r * SROWB + c4 * 16, gAl + (size_t)r * DM + k0 + c4 * 16);
        }
        {                                         // B: 64 rows x 64B, 4 planes
            int r = tid >> 2, c4 = tid & 3;
            cp16(st + 20480u + r * SROWB + c4 * 16, gB1h + (size_t)r * DM + k0 + c4 * 16);
            cp16(st + 25600u + r * SROWB + c4 * 16, gB1l + (size_t)r * DM + k0 + c4 * 16);
            cp16(st + 30720u + r * SROWB + c4 * 16, gB3h + (size_t)r * DM + k0 + c4 * 16);
            cp16(st + 35840u + r * SROWB + c4 * 16, gB3l + (size_t)r * DM + k0 + c4 * 16);
        }
    };

    int hh1[2][4][4], xx1[2][4][4], hh3[2][4][4], xx3[2][4][4];
#pragma unroll
    for (int mi = 0; mi < 2; mi++)
#pragma unroll
        for (int ni = 0; ni < 4; ni++)
#pragma unroll
            for (int r = 0; r < 4; r++) {
                hh1[mi][ni][r] = 0; xx1[mi][ni][r] = 0;
                hh3[mi][ni][r] = 0; xx3[mi][ni][r] = 0;
            }

    const int NC = DM / 64;   // 16
    issue(0); CP_COMMIT();
    issue(1); CP_COMMIT();

    for (int c = 0; c < NC; c++) {
        CP_WAIT1();
        __syncthreads();
        if (c + 2 < NC) issue(c + 2);
        CP_COMMIT();
        const char* st = dsm + (c % 3) * SSTAGE;
#pragma unroll
        for (int ks = 0; ks < 2; ks++) {
            int kb = ks * 32 + 4 * tg;
            uint32_t ah[2][4], al[2][4];
#pragma unroll
            for (int mi = 0; mi < 2; mi++) {
                int r0 = (wm * 32 + mi * 16 + g) * SROWB;
                int r1 = r0 + 8 * SROWB;
                ah[mi][0] = *(const uint32_t*)(st + r0 + kb);
                ah[mi][1] = *(const uint32_t*)(st + r1 + kb);
                ah[mi][2] = *(const uint32_t*)(st + r0 + kb + 16);
                ah[mi][3] = *(const uint32_t*)(st + r1 + kb + 16);
                al[mi][0] = *(const uint32_t*)(st + 10240 + r0 + kb);
                al[mi][1] = *(const uint32_t*)(st + 10240 + r1 + kb);
                al[mi][2] = *(const uint32_t*)(st + 10240 + r0 + kb + 16);
                al[mi][3] = *(const uint32_t*)(st + 10240 + r1 + kb + 16);
            }
#pragma unroll
            for (int ni = 0; ni < 4; ni++) {
                int rn_ = (wn * 32 + ni * 8 + g) * SROWB;
                uint32_t b1h0 = *(const uint32_t*)(st + 20480 + rn_ + kb);
                uint32_t b1h1 = *(const uint32_t*)(st + 20480 + rn_ + kb + 16);
                uint32_t b1l0 = *(const uint32_t*)(st + 25600 + rn_ + kb);
                uint32_t b1l1 = *(const uint32_t*)(st + 25600 + rn_ + kb + 16);
                uint32_t b3h0 = *(const uint32_t*)(st + 30720 + rn_ + kb);
                uint32_t b3h1 = *(const uint32_t*)(st + 30720 + rn_ + kb + 16);
                uint32_t b3l0 = *(const uint32_t*)(st + 35840 + rn_ + kb);
                uint32_t b3l1 = *(const uint32_t*)(st + 35840 + rn_ + kb + 16);
#pragma unroll
                for (int mi = 0; mi < 2; mi++) {
                    mma_s8(hh1[mi][ni], ah[mi], b1h0, b1h1);
                    mma_s8(xx1[mi][ni], ah[mi], b1l0, b1l1);
                    mma_s8(xx1[mi][ni], al[mi], b1h0, b1h1);
                    mma_s8(hh3[mi][ni], ah[mi], b3h0, b3h1);
                    mma_s8(xx3[mi][ni], ah[mi], b3l0, b3l1);
                    mma_s8(xx3[mi][ni], al[mi], b3h0, b3h1);
                }
            }
        }
    }

    float* H = g_h + (size_t)z * CAP * DFF;
    const float* s1 = g_s1 + e * DFF + n0;
    const float* s3 = g_s3 + e * DFF + n0;
    const float* sa = g_sa + z * CAP;
#pragma unroll
    for (int mi = 0; mi < 2; mi++)
#pragma unroll
        for (int half = 0; half < 2; half++) {
            int m = m0 + wm * 32 + mi * 16 + half * 8 + g;
            if (m < rows) {
                float sm = sa[m];
#pragma unroll
                for (int ni = 0; ni < 4; ni++) {
                    int col = wn * 32 + ni * 8 + 2 * tg;
                    float c1a = sm * s1[col]     * ((float)hh1[mi][ni][half*2+0] + (float)xx1[mi][ni][half*2+0] * (1.f/127.f));
                    float c1b = sm * s1[col + 1] * ((float)hh1[mi][ni][half*2+1] + (float)xx1[mi][ni][half*2+1] * (1.f/127.f));
                    float c3a = sm * s3[col]     * ((float)hh3[mi][ni][half*2+0] + (float)xx3[mi][ni][half*2+0] * (1.f/127.f));
                    float c3b = sm * s3[col + 1] * ((float)hh3[mi][ni][half*2+1] + (float)xx3[mi][ni][half*2+1] * (1.f/127.f));
                    float o0 = (c1a / (1.f + expf(-c1a))) * c3a;
                    float o1 = (c1b / (1.f + expf(-c1b))) * c3b;
                    *(float2*)&H[(size_t)m * DFF + n0 + col] = make_float2(o0, o1);
                }
            }
        }
}

// ---------------- 5. gemm2 int8: block 128M x 128N, warp 64x32, 3-stage ----------------
__global__ __launch_bounds__(256) void gemm2_i8() {
    int z = blockIdx.z, e = z & (NE - 1);
    int rows = g_cnt[z]; if (rows > CAP) rows = CAP;
    int m0 = blockIdx.y * 128; if (m0 >= rows) return;
    int n0 = blockIdx.x * 128;

    extern __shared__ char dsm[];
    uint32_t sb = smem_u32(dsm);

    const char* gAh = (const char*)g_hh  + (size_t)z * CAP * DFF + (size_t)m0 * DFF;
    const char* gAl = (const char*)g_hl  + (size_t)z * CAP * DFF + (size_t)m0 * DFF;
    const char* gBh = (const char*)g_w2h + (size_t)e * DM * DFF + (size_t)n0 * DFF;
    const char* gBl = (const char*)g_w2l + (size_t)e * DM * DFF + (size_t)n0 * DFF;

    int tid = threadIdx.x, wid = tid >> 5, lane = tid & 31;
    int wm = wid >> 2, wn = wid & 3;             // 2m x 4n warps
    int g = lane >> 2, tg = lane & 3;

    auto issue = [&](int c) {
        uint32_t st = sb + (uint32_t)(c % 3) * SSTAGE;
        int k0 = c * 64;
#pragma unroll
        for (int i = 0; i < 2; i++) {
            int f = tid + i * 256, r = f >> 2, c4 = f & 3;
            cp16(st + r * SROWB + c4 * 16,          gAh + (size_t)r * DFF + k0 + c4 * 16);
            cp16(st + 10240u + r * SROWB + c4 * 16, gAl + (size_t)r * DFF + k0 + c4 * 16);
            cp16(st + 20480u + r * SROWB + c4 * 16, gBh + (size_t)r * DFF + k0 + c4 * 16);
            cp16(st + 30720u + r * SROWB + c4 * 16, gBl + (size_t)r * DFF + k0 + c4 * 16);
        }
    };

    int hh[4][4][4], xx[4][4][4];
#pragma unroll
    for (int mi = 0; mi < 4; mi++)
#pragma unroll
        for (int ni = 0; ni < 4; ni++)
#pragma unroll
            for (int r = 0; r < 4; r++) { hh[mi][ni][r] = 0; xx[mi][ni][r] = 0; }

    const int NC = DFF / 64;  // 64
    issue(0); CP_COMMIT();
    issue(1); CP_COMMIT();

    for (int c = 0; c < NC; c++) {
        CP_WAIT1();
        __syncthreads();
        if (c + 2 < NC) issue(c + 2);
        CP_COMMIT();
        const char* st = dsm + (c % 3) * SSTAGE;
#pragma unroll
        for (int ks = 0; ks < 2; ks++) {
            int kb = ks * 32 + 4 * tg;
            uint32_t ah[4][4], al[4][4];
#pragma unroll
            for (int mi = 0; mi < 4; mi++) {
                int r0 = (wm * 64 + mi * 16 + g) * SROWB;
                int r1 = r0 + 8 * SROWB;
                ah[mi][0] = *(const uint32_t*)(st + r0 + kb);
                ah[mi][1] = *(const uint32_t*)(st + r1 + kb);
                ah[mi][2] = *(const uint32_t*)(st + r0 + kb + 16);
                ah[mi][3] = *(const uint32_t*)(st + r1 + kb + 16);
                al[mi][0] = *(const uint32_t*)(st + 10240 + r0 + kb);
                al[mi][1] = *(const uint32_t*)(st + 10240 + r1 + kb);
                al[mi][2] = *(const uint32_t*)(st + 10240 + r0 + kb + 16);
                al[mi][3] = *(const uint32_t*)(st + 10240 + r1 + kb + 16);
            }
#pragma unroll
            for (int ni = 0; ni < 4; ni++) {
                int rn_ = (wn * 32 + ni * 8 + g) * SROWB;
                uint32_t bh0 = *(const uint32_t*)(st + 20480 + rn_ + kb);
                uint32_t bh1 = *(const uint32_t*)(st + 20480 + rn_ + kb + 16);
                uint32_t bl0 = *(const uint32_t*)(st + 30720 + rn_ + kb);
                uint32_t bl1 = *(const uint32_t*)(st + 30720 + rn_ + kb + 16);
#pragma unroll
                for (int mi = 0; mi < 4; mi++) {
                    mma_s8(hh[mi][ni], ah[mi], bh0, bh1);
                    mma_s8(xx[mi][ni], ah[mi], bl0, bl1);
                    mma_s8(xx[mi][ni], al[mi], bh0, bh1);
                }
            }
        }
    }

    float* O = g_ob + (size_t)z * CAP * DM;
    const float* s2 = g_s2 + e * DM + n0;
    const float* sh = g_sh + z * CAP;
#pragma unroll
    for (int mi = 0; mi < 4; mi++)
#pragma unroll
        for (int half = 0; half < 2; half++) {
            int m = m0 + wm * 64 + mi * 16 + half * 8 + g;
            if (m < rows) {
                float sm = sh[m];
#pragma unroll
                for (int ni = 0; ni < 4; ni++) {
                    int col = wn * 32 + ni * 8 + 2 * tg;
                    float o0 = sm * s2[col]     * ((float)hh[mi][ni][half*2+0] + (float)xx[mi][ni][half*2+0] * (1.f/127.f));
                    float o1 = sm * s2[col + 1] * ((float)hh[mi][ni][half*2+1] + (float)xx[mi][ni][half*2+1] * (1.f/127.f));
                    *(float2*)&O[(size_t)m * DM + n0 + col] = make_float2(o0, o1);
                }
            }
        }
}

// ---------------- 6. weighted scatter/combine ----------------
__global__ __launch_bounds__(256) void scatter_kernel(float* __restrict__ out) {
    int t = blockIdx.x;
    int d4 = threadIdx.x;
    float4 acc = {0.f, 0.f, 0.f, 0.f};
#pragma unroll
    for (int k = 0; k < TOPK; k++) {
        int tk = t * 2 + k;
        int pos = g_pos[tk];
        if (pos < CAP) {
            int e = g_top_idx[tk];
            float w = g_top_w[tk];
            float4 v = ((const float4*)(g_ob + ((size_t)(k * NE + e) * CAP + pos) * DM))[d4];
            acc.x += v.x * w; acc.y += v.y * w; acc.z += v.z * w; acc.w += v.w * w;
        }
    }
    ((float4*)(out + (size_t)t * DM))[d4] = acc;
}

// ---------------- 7. aux loss ----------------
__global__ __launch_bounds__(256) void aux_kernel(float* __restrict__ out, int out_size) {
    __shared__ float red[256];
    __shared__ float Ps[NE];
    int tid = threadIdx.x;
    float loc[NE];
#pragma unroll
    for (int e = 0; e < NE; e++) loc[e] = 0.f;
    for (int i = tid; i < N_TOK; i += 256) {
#pragma unroll
        for (int e = 0; e < NE; e++) loc[e] += g_probs[i * NE + e];
    }
    for (int e = 0; e < NE; e++) {
        red[tid] = loc[e];
        __syncthreads();
        for (int s = 128; s > 0; s >>= 1) {
            if (tid < s) red[tid] += red[tid + s];
            __syncthreads();
        }
        if (tid == 0) Ps[e] = red[0];
        __syncthreads();
    }
    if (tid == 0) {
        float aux = 0.f;
        for (int e = 0; e < NE; e++) {
            float f = (float)(g_cnt[e] + g_cnt[NE + e]) / (float)(N_TOK * TOPK);
            float P = Ps[e] / (float)N_TOK;
            aux += f * P;
        }
        out[out_size - 1] = aux * (float)NE;
    }
}

// ---------------- launch ----------------
extern "C" void kernel_launch(void* const* d_in, const int* in_sizes, int n_in,
                              void* d_out, int out_size) {
    const float* x  = (const float*)d_in[0];
    const float* gw = (const float*)d_in[1];
    const float* w1 = (const float*)d_in[2];
    const float* w2 = (const float*)d_in[3];
    const float* w3 = (const float*)d_in[4];
    float* out = (float*)d_out;

    const int SMEM = 3 * SSTAGE;   // 122880
    cudaFuncSetAttribute(gemm13_i8, cudaFuncAttributeMaxDynamicSharedMemorySize, SMEM);
    cudaFuncSetAttribute(gemm2_i8,  cudaFuncAttributeMaxDynamicSharedMemorySize, SMEM);

    uint32_t *w1h, *w1l, *w3h, *w3l, *w2h, *w2l;
    float *s1, *s3, *s2, *hp, *shp;
    uint32_t *hh, *hl;
    int* cntp;
    cudaGetSymbolAddress((void**)&w1h, g_w1h); cudaGetSymbolAddress((void**)&w1l, g_w1l);
    cudaGetSymbolAddress((void**)&w3h, g_w3h); cudaGetSymbolAddress((void**)&w3l, g_w3l);
    cudaGetSymbolAddress((void**)&w2h, g_w2h); cudaGetSymbolAddress((void**)&w2l, g_w2l);
    cudaGetSymbolAddress((void**)&s1, g_s1);   cudaGetSymbolAddress((void**)&s3, g_s3);
    cudaGetSymbolAddress((void**)&s2, g_s2);
    cudaGetSymbolAddress((void**)&hp, g_h);
    cudaGetSymbolAddress((void**)&hh, g_hh);   cudaGetSymbolAddress((void**)&hl, g_hl);
    cudaGetSymbolAddress((void**)&shp, g_sh);  cudaGetSymbolAddress((void**)&cntp, g_cnt);

    // quantize weights (per output-channel row over K)
    qrow_kernel<<<NE * DFF, 256>>>(w1, w1h, w1l, s1, DM, 0, nullptr);
    qrow_kernel<<<NE * DFF, 256>>>(w3, w3h, w3l, s3, DM, 0, nullptr);
    qrow_kernel<<<NE * DM,  256>>>(w2, w2h, w2l, s2, DFF, 0, nullptr);

    router_kernel<<<N_TOK / 8, 256>>>(x, gw);
    scan_kernel<<<2, 256>>>();
    gather_quant<<<N_TOK * TOPK, 256>>>(x);

    dim3 g1(DFF / 64, CAP / 128, TOPK * NE);    // 64 x 10 x 16
    gemm13_i8<<<g1, 256, SMEM>>>();

    // quantize h rows (valid rows only)
    qrow_kernel<<<TOPK * NE * CAP, 256>>>(hp, hh, hl, shp, DFF, CAP, cntp);

    dim3 g2(DM / 128, CAP / 128, TOPK * NE);    // 8 x 10 x 16
    gemm2_i8<<<g2, 256, SMEM>>>();

    scatter_kernel<<<N_TOK, 256>>>(out);
    aux_kernel<<<1, 256>>>(out, out_size);
}

// round 8
// speedup vs baseline: 3.5009x; 3.5009x over previous
#include <cuda_runtime.h>
#include <math.h>
#include <stdint.h>

#define N_TOK 8192
#define DM    1024
#define DFF   4096
#define NE    8
#define TOPK  2
#define CAP   1280
#define PAD   36          // smem row stride in floats
#define SROWB 144         // row stride bytes
#define SSTAGE 55296      // bytes per pipeline stage (384 rows x 144B)
#define NSTAGE 4

// ---------------- scratch ----------------
__device__ float g_buf[2 * NE * CAP * DM];
__device__ float g_h  [2 * NE * CAP * DFF];
__device__ float g_ob [2 * NE * CAP * DM];
__device__ float g_w1t[NE * DFF * DM];
__device__ float g_w3t[NE * DFF * DM];
__device__ float g_w2t[NE * DM * DFF];
__device__ float g_probs[N_TOK * NE];
__device__ int   g_top_idx[N_TOK * TOPK];
__device__ float g_top_w [N_TOK * TOPK];
__device__ int   g_pos   [N_TOK * TOPK];
__device__ int   g_cnt   [TOPK * NE];

// ---------------- helpers ----------------
__device__ __forceinline__ uint32_t smem_u32(const void* p) {
    uint32_t a;
    asm("{ .reg .u64 t; cvta.to.shared.u64 t, %1; cvt.u32.u64 %0, t; }" : "=r"(a) : "l"(p));
    return a;
}
__device__ __forceinline__ float tf32f(float x) {
    uint32_t r; asm("cvt.rna.tf32.f32 %0, %1;" : "=r"(r) : "f"(x));
    return __uint_as_float(r);
}
__device__ __forceinline__ void mma_tf32(float* c, const uint32_t* a, uint32_t b0, uint32_t b1) {
    asm volatile(
        "mma.sync.aligned.m16n8k8.row.col.f32.tf32.tf32.f32 "
        "{%0,%1,%2,%3}, {%4,%5,%6,%7}, {%8,%9}, {%0,%1,%2,%3};"
        : "+f"(c[0]), "+f"(c[1]), "+f"(c[2]), "+f"(c[3])
        : "r"(a[0]), "r"(a[1]), "r"(a[2]), "r"(a[3]), "r"(b0), "r"(b1));
}
__device__ __forceinline__ void cp16(uint32_t s, const void* g) {
    asm volatile("cp.async.cg.shared.global [%0], [%1], 16;" :: "r"(s), "l"(g) : "memory");
}
#define CP_COMMIT() asm volatile("cp.async.commit_group;" ::: "memory")
#define CP_WAIT2()  asm volatile("cp.async.wait_group 2;" ::: "memory")

// ---------------- 0. weight convert (fp32 -> tf32-rounded fp32) ----------------
__global__ __launch_bounds__(256) void cvt_kernel(const float4* __restrict__ src,
                                                  float4* __restrict__ dst, int n4) {
    int i = blockIdx.x * blockDim.x + threadIdx.x;
    if (i < n4) {
        float4 v = src[i];
        v.x = tf32f(v.x); v.y = tf32f(v.y); v.z = tf32f(v.z); v.w = tf32f(v.w);
        dst[i] = v;
    }
}

// ---------------- 1. router ----------------
__global__ __launch_bounds__(256) void router_kernel(const float* __restrict__ x,
                                                     const float* __restrict__ gw) {
    int warp = (blockIdx.x * blockDim.x + threadIdx.x) >> 5;
    int lane = threadIdx.x & 31;
    if (warp >= N_TOK) return;
    const float* xr = x + (size_t)warp * DM;
    float acc[NE];
#pragma unroll
    for (int e = 0; e < NE; e++) acc[e] = 0.f;
    for (int i = lane; i < DM; i += 32) {
        float xv = xr[i];
#pragma unroll
        for (int e = 0; e < NE; e++) acc[e] += xv * gw[e * DM + i];
    }
#pragma unroll
    for (int off = 16; off > 0; off >>= 1)
#pragma unroll
        for (int e = 0; e < NE; e++) acc[e] += __shfl_xor_sync(0xffffffffu, acc[e], off);
    if (lane == 0) {
        float mx = acc[0];
#pragma unroll
        for (int e = 1; e < NE; e++) mx = fmaxf(mx, acc[e]);
        float p[NE], s = 0.f;
#pragma unroll
        for (int e = 0; e < NE; e++) { p[e] = expf(acc[e] - mx); s += p[e]; }
        float inv = 1.f / s;
        int i0 = 0;
#pragma unroll
        for (int e = 1; e < NE; e++) if (p[e] > p[i0]) i0 = e;
        int i1 = (i0 == 0) ? 1 : 0;
#pragma unroll
        for (int e = 0; e < NE; e++) if (e != i0 && e != i1 && p[e] > p[i1]) i1 = e;
#pragma unroll
        for (int e = 0; e < NE; e++) g_probs[warp * NE + e] = p[e] * inv;
        float p0 = p[i0] * inv, p1 = p[i1] * inv;
        float ws = p0 + p1 + 1e-10f;
        g_top_idx[warp * 2 + 0] = i0;  g_top_w[warp * 2 + 0] = p0 / ws;
        g_top_idx[warp * 2 + 1] = i1;  g_top_w[warp * 2 + 1] = p1 / ws;
    }
}

// ---------------- 2. capacity scan ----------------
__global__ __launch_bounds__(256) void scan_kernel() {
    int k = blockIdx.x;
    int t = threadIdx.x;
    const int CH = N_TOK / 256;
    __shared__ int cnt[256][NE];
    int local[NE];
#pragma unroll
    for (int e = 0; e < NE; e++) local[e] = 0;
    for (int i = 0; i < CH; i++) local[g_top_idx[(t * CH + i) * 2 + k]]++;
#pragma unroll
    for (int e = 0; e < NE; e++) cnt[t][e] = local[e];
    __syncthreads();
    if (t < NE) {
        int run = 0;
        for (int i = 0; i < 256; i++) { int v = cnt[i][t]; cnt[i][t] = run; run += v; }
        g_cnt[k * NE + t] = run;
    }
    __syncthreads();
    int off[NE];
#pragma unroll
    for (int e = 0; e < NE; e++) off[e] = cnt[t][e];
    for (int i = 0; i < CH; i++) {
        int tk = (t * CH + i) * 2 + k;
        g_pos[tk] = off[g_top_idx[tk]]++;
    }
}

// ---------------- 3. gather (tf32 rounding of A at write) ----------------
__global__ __launch_bounds__(256) void gather_kernel(const float* __restrict__ x) {
    int tk = blockIdx.x;
    int pos = g_pos[tk];
    if (pos >= CAP) return;
    int e = g_top_idx[tk];
    int k = tk & 1, t = tk >> 1;
    float4*       dst = (float4*)(g_buf + ((size_t)(k * NE + e) * CAP + pos) * DM);
    const float4* src = (const float4*)(x + (size_t)t * DM);
    float4 v = src[threadIdx.x];
    v.x = tf32f(v.x); v.y = tf32f(v.y); v.z = tf32f(v.z); v.w = tf32f(v.w);
    dst[threadIdx.x] = v;
}

// ---------------- 4. gemm13: 128M x 128N(x2), warp 64x32(x2), 4-stage, 1 barrier/chunk ----------------
__global__ __launch_bounds__(256) void gemm13_mma(const float* __restrict__ W1,
                                                  const float* __restrict__ W3) {
    int z = blockIdx.z, e = z & (NE - 1);
    int rows = g_cnt[z]; if (rows > CAP) rows = CAP;
    int m0 = blockIdx.y * 128; if (m0 >= rows) return;
    int n0 = blockIdx.x * 128;

    extern __shared__ char dsm[];
    uint32_t sb = smem_u32(dsm);

    const float* gA  = g_buf + (size_t)z * CAP * DM + (size_t)m0 * DM;
    const float* gB1 = W1 + (size_t)e * DFF * DM + (size_t)n0 * DM;
    const float* gB3 = W3 + (size_t)e * DFF * DM + (size_t)n0 * DM;

    int tid = threadIdx.x, wid = tid >> 5, lane = tid & 31;
    int wm = wid >> 2, wn = wid & 3;
    int g = lane >> 2, tg = lane & 3;

    auto issue = [&](int c) {
        uint32_t st = sb + (uint32_t)(c % NSTAGE) * SSTAGE;
        int k0 = c * 32;
#pragma unroll
        for (int i = 0; i < 4; i++) {
            int f = tid + i * 256, r = f >> 3, c4 = f & 7;
            cp16(st + r * SROWB + c4 * 16, gA + (size_t)r * DM + k0 + c4 * 4);
        }
#pragma unroll
        for (int i = 0; i < 4; i++) {
            int f = tid + i * 256, r = f >> 3, c4 = f & 7;
            cp16(st + 18432u + r * SROWB + c4 * 16, gB1 + (size_t)r * DM + k0 + c4 * 4);
        }
#pragma unroll
        for (int i = 0; i < 4; i++) {
            int f = tid + i * 256, r = f >> 3, c4 = f & 7;
            cp16(st + 36864u + r * SROWB + c4 * 16, gB3 + (size_t)r * DM + k0 + c4 * 4);
        }
    };

    float acc1[4][4][4], acc2[4][4][4];
#pragma unroll
    for (int mi = 0; mi < 4; mi++)
#pragma unroll
        for (int ni = 0; ni < 4; ni++)
#pragma unroll
            for (int r = 0; r < 4; r++) { acc1[mi][ni][r] = 0.f; acc2[mi][ni][r] = 0.f; }

    uint32_t af[2][4][4], b1f[2][4][2], b3f[2][4][2];

    auto loadfrag = [&](const float* As, const float* B1s, const float* B3s, int kk, int buf) {
        int k = kk * 8;
#pragma unroll
        for (int mi = 0; mi < 4; mi++) {
            int mb = wm * 64 + mi * 16;
            af[buf][mi][0] = __float_as_uint(As[(mb + g) * PAD + k + tg]);
            af[buf][mi][1] = __float_as_uint(As[(mb + 8 + g) * PAD + k + tg]);
            af[buf][mi][2] = __float_as_uint(As[(mb + g) * PAD + k + 4 + tg]);
            af[buf][mi][3] = __float_as_uint(As[(mb + 8 + g) * PAD + k + 4 + tg]);
        }
#pragma unroll
        for (int ni = 0; ni < 4; ni++) {
            int nb = wn * 32 + ni * 8;
            b1f[buf][ni][0] = __float_as_uint(B1s[(nb + g) * PAD + k + tg]);
            b1f[buf][ni][1] = __float_as_uint(B1s[(nb + g) * PAD + k + 4 + tg]);
            b3f[buf][ni][0] = __float_as_uint(B3s[(nb + g) * PAD + k + tg]);
            b3f[buf][ni][1] = __float_as_uint(B3s[(nb + g) * PAD + k + 4 + tg]);
        }
    };

    const int NC = DM / 32;   // 32
    issue(0); CP_COMMIT();
    issue(1); CP_COMMIT();
    issue(2); CP_COMMIT();

    for (int c = 0; c < NC; c++) {
        CP_WAIT2();
        __syncthreads();                  // single barrier per chunk
        if (c + 3 < NC) issue(c + 3);
        CP_COMMIT();
        const float* As  = (const float*)(dsm + (c % NSTAGE) * SSTAGE);
        const float* B1s = As + 18432 / 4;
        const float* B3s = As + 36864 / 4;
        loadfrag(As, B1s, B3s, 0, 0);
#pragma unroll
        for (int kk = 0; kk < 4; kk++) {
            int cur = kk & 1;
            if (kk < 3) loadfrag(As, B1s, B3s, kk + 1, cur ^ 1);
#pragma unroll
            for (int ni = 0; ni < 4; ni++) {
#pragma unroll
                for (int mi = 0; mi < 4; mi++)
                    mma_tf32(acc1[mi][ni], af[cur][mi], b1f[cur][ni][0], b1f[cur][ni][1]);
#pragma unroll
                for (int mi = 0; mi < 4; mi++)
                    mma_tf32(acc2[mi][ni], af[cur][mi], b3f[cur][ni][0], b3f[cur][ni][1]);
            }
        }
    }

    float* H = g_h + (size_t)z * CAP * DFF;
#pragma unroll
    for (int mi = 0; mi < 4; mi++)
#pragma unroll
        for (int half = 0; half < 2; half++) {
            int m = m0 + wm * 64 + mi * 16 + half * 8 + g;
            if (m < rows) {
#pragma unroll
                for (int ni = 0; ni < 4; ni++) {
                    float v0 = acc1[mi][ni][half * 2 + 0];
                    float v1 = acc1[mi][ni][half * 2 + 1];
                    float o0 = tf32f((v0 / (1.f + expf(-v0))) * acc2[mi][ni][half * 2 + 0]);
                    float o1 = tf32f((v1 / (1.f + expf(-v1))) * acc2[mi][ni][half * 2 + 1]);
                    int col = n0 + wn * 32 + ni * 8 + 2 * tg;
                    *(float2*)&H[(size_t)m * DFF + col] = make_float2(o0, o1);
                }
            }
        }
}

// ---------------- 5. gemm2: 128M x 256N, warp 64x64, 4-stage, 1 barrier/chunk ----------------
__global__ __launch_bounds__(256) void gemm2_mma(const float* __restrict__ W2) {
    int z = blockIdx.z, e = z & (NE - 1);
    int rows = g_cnt[z]; if (rows > CAP) rows = CAP;
    int m0 = blockIdx.y * 128; if (m0 >= rows) return;
    int n0 = blockIdx.x * 256;

    extern __shared__ char dsm[];
    uint32_t sb = smem_u32(dsm);

    const float* gA = g_h + (size_t)z * CAP * DFF + (size_t)m0 * DFF;
    const float* gB = W2  + (size_t)e * DM * DFF + (size_t)n0 * DFF;

    int tid = threadIdx.x, wid = tid >> 5, lane = tid & 31;
    int wm = wid >> 2, wn = wid & 3;
    int g = lane >> 2, tg = lane & 3;

    auto issue = [&](int c) {
        uint32_t st = sb + (uint32_t)(c % NSTAGE) * SSTAGE;
        int k0 = c * 32;
#pragma unroll
        for (int i = 0; i < 4; i++) {
            int f = tid + i * 256, r = f >> 3, c4 = f & 7;
            cp16(st + r * SROWB + c4 * 16, gA + (size_t)r * DFF + k0 + c4 * 4);
        }
#pragma unroll
        for (int i = 0; i < 8; i++) {
            int f = tid + i * 256, r = f >> 3, c4 = f & 7;
            cp16(st + 18432u + r * SROWB + c4 * 16, gB + (size_t)r * DFF + k0 + c4 * 4);
        }
    };

    float acc[4][8][4];
#pragma unroll
    for (int mi = 0; mi < 4; mi++)
#pragma unroll
        for (int ni = 0; ni < 8; ni++)
#pragma unroll
            for (int r = 0; r < 4; r++) acc[mi][ni][r] = 0.f;

    uint32_t af[2][4][4], bf[2][8][2];

    auto loadfrag = [&](const float* As, const float* Bs, int kk, int buf) {
        int k = kk * 8;
#pragma unroll
        for (int mi = 0; mi < 4; mi++) {
            int mb = wm * 64 + mi * 16;
            af[buf][mi][0] = __float_as_uint(As[(mb + g) * PAD + k + tg]);
            af[buf][mi][1] = __float_as_uint(As[(mb + 8 + g) * PAD + k + tg]);
            af[buf][mi][2] = __float_as_uint(As[(mb + g) * PAD + k + 4 + tg]);
            af[buf][mi][3] = __float_as_uint(As[(mb + 8 + g) * PAD + k + 4 + tg]);
        }
#pragma unroll
        for (int ni = 0; ni < 8; ni++) {
            int nb = wn * 64 + ni * 8;
            bf[buf][ni][0] = __float_as_uint(Bs[(nb + g) * PAD + k + tg]);
            bf[buf][ni][1] = __float_as_uint(Bs[(nb + g) * PAD + k + 4 + tg]);
        }
    };

    const int NC = DFF / 32;  // 128
    issue(0); CP_COMMIT();
    issue(1); CP_COMMIT();
    issue(2); CP_COMMIT();

    for (int c = 0; c < NC; c++) {
        CP_WAIT2();
        __syncthreads();
        if (c + 3 < NC) issue(c + 3);
        CP_COMMIT();
        const float* As = (const float*)(dsm + (c % NSTAGE) * SSTAGE);
        const float* Bs = As + 18432 / 4;
        loadfrag(As, Bs, 0, 0);
#pragma unroll
        for (int kk = 0; kk < 4; kk++) {
            int cur = kk & 1;
            if (kk < 3) loadfrag(As, Bs, kk + 1, cur ^ 1);
#pragma unroll
            for (int ni = 0; ni < 8; ni++)
#pragma unroll
                for (int mi = 0; mi < 4; mi++)
                    mma_tf32(acc[mi][ni], af[cur][mi], bf[cur][ni][0], bf[cur][ni][1]);
        }
    }

    float* O = g_ob + (size_t)z * CAP * DM;
#pragma unroll
    for (int mi = 0; mi < 4; mi++)
#pragma unroll
        for (int half = 0; half < 2; half++) {
            int m = m0 + wm * 64 + mi * 16 + half * 8 + g;
            if (m < rows) {
#pragma unroll
                for (int ni = 0; ni < 8; ni++) {
                    int col = n0 + wn * 64 + ni * 8 + 2 * tg;
                    *(float2*)&O[(size_t)m * DM + col] =
                        make_float2(acc[mi][ni][half * 2 + 0], acc[mi][ni][half * 2 + 1]);
                }
            }
        }
}

// ---------------- 6. weighted scatter/combine ----------------
__global__ __launch_bounds__(256) void scatter_kernel(float* __restrict__ out) {
    int t = blockIdx.x;
    int d4 = threadIdx.x;
    float4 acc = {0.f, 0.f, 0.f, 0.f};
#pragma unroll
    for (int k = 0; k < TOPK; k++) {
        int tk = t * 2 + k;
        int pos = g_pos[tk];
        if (pos < CAP) {
            int e = g_top_idx[tk];
            float w = g_top_w[tk];
            float4 v = ((const float4*)(g_ob + ((size_t)(k * NE + e) * CAP + pos) * DM))[d4];
            acc.x += v.x * w; acc.y += v.y * w; acc.z += v.z * w; acc.w += v.w * w;
        }
    }
    ((float4*)(out + (size_t)t * DM))[d4] = acc;
}

// ---------------- 7. aux loss ----------------
__global__ __launch_bounds__(256) void aux_kernel(float* __restrict__ out, int out_size) {
    __shared__ float red[256];
    __shared__ float Ps[NE];
    int tid = threadIdx.x;
    float loc[NE];
#pragma unroll
    for (int e = 0; e < NE; e++) loc[e] = 0.f;
    for (int i = tid; i < N_TOK; i += 256) {
#pragma unroll
        for (int e = 0; e < NE; e++) loc[e] += g_probs[i * NE + e];
    }
    for (int e = 0; e < NE; e++) {
        red[tid] = loc[e];
        __syncthreads();
        for (int s = 128; s > 0; s >>= 1) {
            if (tid < s) red[tid] += red[tid + s];
            __syncthreads();
        }
        if (tid == 0) Ps[e] = red[0];
        __syncthreads();
    }
    if (tid == 0) {
        float aux = 0.f;
        for (int e = 0; e < NE; e++) {
            float f = (float)(g_cnt[e] + g_cnt[NE + e]) / (float)(N_TOK * TOPK);
            float P = Ps[e] / (float)N_TOK;
            aux += f * P;
        }
        out[out_size - 1] = aux * (float)NE;
    }
}

// ---------------- launch ----------------
extern "C" void kernel_launch(void* const* d_in, const int* in_sizes, int n_in,
                              void* d_out, int out_size) {
    const float* x  = (const float*)d_in[0];
    const float* gw = (const float*)d_in[1];
    const float* w1 = (const float*)d_in[2];
    const float* w2 = (const float*)d_in[3];
    const float* w3 = (const float*)d_in[4];
    float* out = (float*)d_out;

    const int SMEM = NSTAGE * SSTAGE;   // 221184
    cudaFuncSetAttribute(gemm13_mma, cudaFuncAttributeMaxDynamicSharedMemorySize, SMEM);
    cudaFuncSetAttribute(gemm2_mma,  cudaFuncAttributeMaxDynamicSharedMemorySize, SMEM);

    float* w1t; cudaGetSymbolAddress((void**)&w1t, g_w1t);
    float* w3t; cudaGetSymbolAddress((void**)&w3t, g_w3t);
    float* w2t; cudaGetSymbolAddress((void**)&w2t, g_w2t);

    const int N4 = NE * DFF * DM / 4;
    cvt_kernel<<<(N4 + 255) / 256, 256>>>((const float4*)w1, (float4*)w1t, N4);
    cvt_kernel<<<(N4 + 255) / 256, 256>>>((const float4*)w3, (float4*)w3t, N4);
    cvt_kernel<<<(N4 + 255) / 256, 256>>>((const float4*)w2, (float4*)w2t, N4);

    router_kernel<<<N_TOK / 8, 256>>>(x, gw);
    scan_kernel<<<2, 256>>>();
    gather_kernel<<<N_TOK * TOPK, 256>>>(x);

    dim3 g1(DFF / 128, CAP / 128, TOPK * NE);   // 32 x 10 x 16
    gemm13_mma<<<g1, 256, SMEM>>>(w1t, w3t);

    dim3 g2(DM / 256, CAP / 128, TOPK * NE);    // 4 x 10 x 16
    gemm2_mma<<<g2, 256, SMEM>>>(w2t);

    scatter_kernel<<<N_TOK, 256>>>(out);
    aux_kernel<<<1, 256>>>(out, out_size);
}

// round 9
// speedup vs baseline: 3.5160x; 1.0043x over previous
#include <cuda_runtime.h>
#include <math.h>
#include <stdint.h>

#define N_TOK 8192
#define DM    1024
#define DFF   4096
#define NE    8
#define TOPK  2
#define CAP   1280
#define PAD   36          // smem row stride in floats
#define SROWB 144         // row stride bytes
#define SSTAGE 55296      // bytes per pipeline stage (384 rows x 144B)
#define NSTAGE 4

// ---------------- scratch ----------------
__device__ float g_buf[2 * NE * CAP * DM];
__device__ float g_h  [2 * NE * CAP * DFF];
__device__ float g_ob [2 * NE * CAP * DM];
__device__ float g_w1t[NE * DFF * DM];
__device__ float g_w3t[NE * DFF * DM];
__device__ float g_w2t[NE * DM * DFF];
__device__ float g_probs[N_TOK * NE];
__device__ int   g_top_idx[N_TOK * TOPK];
__device__ float g_top_w [N_TOK * TOPK];
__device__ int   g_pos   [N_TOK * TOPK];
__device__ int   g_cnt   [TOPK * NE];

// ---------------- helpers ----------------
__device__ __forceinline__ uint32_t smem_u32(const void* p) {
    uint32_t a;
    asm("{ .reg .u64 t; cvta.to.shared.u64 t, %1; cvt.u32.u64 %0, t; }" : "=r"(a) : "l"(p));
    return a;
}
__device__ __forceinline__ float tf32f(float x) {
    uint32_t r; asm("cvt.rna.tf32.f32 %0, %1;" : "=r"(r) : "f"(x));
    return __uint_as_float(r);
}
__device__ __forceinline__ void mma_tf32(float* c, const uint32_t* a, uint32_t b0, uint32_t b1) {
    asm volatile(
        "mma.sync.aligned.m16n8k8.row.col.f32.tf32.tf32.f32 "
        "{%0,%1,%2,%3}, {%4,%5,%6,%7}, {%8,%9}, {%0,%1,%2,%3};"
        : "+f"(c[0]), "+f"(c[1]), "+f"(c[2]), "+f"(c[3])
        : "r"(a[0]), "r"(a[1]), "r"(a[2]), "r"(a[3]), "r"(b0), "r"(b1));
}
__device__ __forceinline__ void cp16(uint32_t s, const void* g) {
    asm volatile("cp.async.cg.shared.global [%0], [%1], 16;" :: "r"(s), "l"(g) : "memory");
}
#define CP_COMMIT() asm volatile("cp.async.commit_group;" ::: "memory")
#define CP_WAIT2()  asm volatile("cp.async.wait_group 2;" ::: "memory")

// ---------------- 0. weight convert (fp32 -> tf32-rounded fp32) ----------------
__global__ __launch_bounds__(256) void cvt_kernel(const float4* __restrict__ src,
                                                  float4* __restrict__ dst, int n4) {
    int i = blockIdx.x * blockDim.x + threadIdx.x;
    if (i < n4) {
        float4 v = src[i];
        v.x = tf32f(v.x); v.y = tf32f(v.y); v.z = tf32f(v.z); v.w = tf32f(v.w);
        dst[i] = v;
    }
}

// ---------------- 1. router ----------------
__global__ __launch_bounds__(256) void router_kernel(const float* __restrict__ x,
                                                     const float* __restrict__ gw) {
    int warp = (blockIdx.x * blockDim.x + threadIdx.x) >> 5;
    int lane = threadIdx.x & 31;
    if (warp >= N_TOK) return;
    const float* xr = x + (size_t)warp * DM;
    float acc[NE];
#pragma unroll
    for (int e = 0; e < NE; e++) acc[e] = 0.f;
    for (int i = lane; i < DM; i += 32) {
        float xv = xr[i];
#pragma unroll
        for (int e = 0; e < NE; e++) acc[e] += xv * gw[e * DM + i];
    }
#pragma unroll
    for (int off = 16; off > 0; off >>= 1)
#pragma unroll
        for (int e = 0; e < NE; e++) acc[e] += __shfl_xor_sync(0xffffffffu, acc[e], off);
    if (lane == 0) {
        float mx = acc[0];
#pragma unroll
        for (int e = 1; e < NE; e++) mx = fmaxf(mx, acc[e]);
        float p[NE], s = 0.f;
#pragma unroll
        for (int e = 0; e < NE; e++) { p[e] = expf(acc[e] - mx); s += p[e]; }
        float inv = 1.f / s;
        int i0 = 0;
#pragma unroll
        for (int e = 1; e < NE; e++) if (p[e] > p[i0]) i0 = e;
        int i1 = (i0 == 0) ? 1 : 0;
#pragma unroll
        for (int e = 0; e < NE; e++) if (e != i0 && e != i1 && p[e] > p[i1]) i1 = e;
#pragma unroll
        for (int e = 0; e < NE; e++) g_probs[warp * NE + e] = p[e] * inv;
        float p0 = p[i0] * inv, p1 = p[i1] * inv;
        float ws = p0 + p1 + 1e-10f;
        g_top_idx[warp * 2 + 0] = i0;  g_top_w[warp * 2 + 0] = p0 / ws;
        g_top_idx[warp * 2 + 1] = i1;  g_top_w[warp * 2 + 1] = p1 / ws;
    }
}

// ---------------- 2. capacity scan ----------------
__global__ __launch_bounds__(256) void scan_kernel() {
    int k = blockIdx.x;
    int t = threadIdx.x;
    const int CH = N_TOK / 256;
    __shared__ int cnt[256][NE];
    int local[NE];
#pragma unroll
    for (int e = 0; e < NE; e++) local[e] = 0;
    for (int i = 0; i < CH; i++) local[g_top_idx[(t * CH + i) * 2 + k]]++;
#pragma unroll
    for (int e = 0; e < NE; e++) cnt[t][e] = local[e];
    __syncthreads();
    if (t < NE) {
        int run = 0;
        for (int i = 0; i < 256; i++) { int v = cnt[i][t]; cnt[i][t] = run; run += v; }
        g_cnt[k * NE + t] = run;
    }
    __syncthreads();
    int off[NE];
#pragma unroll
    for (int e = 0; e < NE; e++) off[e] = cnt[t][e];
    for (int i = 0; i < CH; i++) {
        int tk = (t * CH + i) * 2 + k;
        g_pos[tk] = off[g_top_idx[tk]]++;
    }
}

// ---------------- 3. gather (tf32 rounding of A at write) ----------------
__global__ __launch_bounds__(256) void gather_kernel(const float* __restrict__ x) {
    int tk = blockIdx.x;
    int pos = g_pos[tk];
    if (pos >= CAP) return;
    int e = g_top_idx[tk];
    int k = tk & 1, t = tk >> 1;
    float4*       dst = (float4*)(g_buf + ((size_t)(k * NE + e) * CAP + pos) * DM);
    const float4* src = (const float4*)(x + (size_t)t * DM);
    float4 v = src[threadIdx.x];
    v.x = tf32f(v.x); v.y = tf32f(v.y); v.z = tf32f(v.z); v.w = tf32f(v.w);
    dst[threadIdx.x] = v;
}

// ---------------- 4. gemm13: 128M x 128N(x2), warp 64x32(x2), 4-stage, 1 barrier/chunk ----------------
__global__ __launch_bounds__(256) void gemm13_mma(const float* __restrict__ W1,
                                                  const float* __restrict__ W3) {
    int z = blockIdx.z, e = z & (NE - 1);
    int rows = g_cnt[z]; if (rows > CAP) rows = CAP;
    int m0 = blockIdx.y * 128; if (m0 >= rows) return;
    int n0 = blockIdx.x * 128;

    extern __shared__ char dsm[];
    uint32_t sb = smem_u32(dsm);

    const float* gA  = g_buf + (size_t)z * CAP * DM + (size_t)m0 * DM;
    const float* gB1 = W1 + (size_t)e * DFF * DM + (size_t)n0 * DM;
    const float* gB3 = W3 + (size_t)e * DFF * DM + (size_t)n0 * DM;

    int tid = threadIdx.x, wid = tid >> 5, lane = tid & 31;
    int wm = wid >> 2, wn = wid & 3;
    int g = lane >> 2, tg = lane & 3;

    auto issue = [&](int c) {
        uint32_t st = sb + (uint32_t)(c % NSTAGE) * SSTAGE;
        int k0 = c * 32;
#pragma unroll
        for (int i = 0; i < 4; i++) {
            int f = tid + i * 256, r = f >> 3, c4 = f & 7;
            cp16(st + r * SROWB + c4 * 16, gA + (size_t)r * DM + k0 + c4 * 4);
        }
#pragma unroll
        for (int i = 0; i < 4; i++) {
            int f = tid + i * 256, r = f >> 3, c4 = f & 7;
            cp16(st + 18432u + r * SROWB + c4 * 16, gB1 + (size_t)r * DM + k0 + c4 * 4);
        }
#pragma unroll
        for (int i = 0; i < 4; i++) {
            int f = tid + i * 256, r = f >> 3, c4 = f & 7;
            cp16(st + 36864u + r * SROWB + c4 * 16, gB3 + (size_t)r * DM + k0 + c4 * 4);
        }
    };

    float acc1[4][4][4], acc2[4][4][4];
#pragma unroll
    for (int mi = 0; mi < 4; mi++)
#pragma unroll
        for (int ni = 0; ni < 4; ni++)
#pragma unroll
            for (int r = 0; r < 4; r++) { acc1[mi][ni][r] = 0.f; acc2[mi][ni][r] = 0.f; }

    uint32_t af[2][4][4], b1f[2][4][2], b3f[2][4][2];

    auto loadfrag = [&](const float* As, const float* B1s, const float* B3s, int kk, int buf) {
        int k = kk * 8;
#pragma unroll
        for (int mi = 0; mi < 4; mi++) {
            int mb = wm * 64 + mi * 16;
            af[buf][mi][0] = __float_as_uint(As[(mb + g) * PAD + k + tg]);
            af[buf][mi][1] = __float_as_uint(As[(mb + 8 + g) * PAD + k + tg]);
            af[buf][mi][2] = __float_as_uint(As[(mb + g) * PAD + k + 4 + tg]);
            af[buf][mi][3] = __float_as_uint(As[(mb + 8 + g) * PAD + k + 4 + tg]);
        }
#pragma unroll
        for (int ni = 0; ni < 4; ni++) {
            int nb = wn * 32 + ni * 8;
            b1f[buf][ni][0] = __float_as_uint(B1s[(nb + g) * PAD + k + tg]);
            b1f[buf][ni][1] = __float_as_uint(B1s[(nb + g) * PAD + k + 4 + tg]);
            b3f[buf][ni][0] = __float_as_uint(B3s[(nb + g) * PAD + k + tg]);
            b3f[buf][ni][1] = __float_as_uint(B3s[(nb + g) * PAD + k + 4 + tg]);
        }
    };

    const int NC = DM / 32;   // 32
    issue(0); CP_COMMIT();
    issue(1); CP_COMMIT();
    issue(2); CP_COMMIT();

    for (int c = 0; c < NC; c++) {
        CP_WAIT2();
        __syncthreads();                  // single barrier per chunk
        if (c + 3 < NC) issue(c + 3);
        CP_COMMIT();
        const float* As  = (const float*)(dsm + (c % NSTAGE) * SSTAGE);
        const float* B1s = As + 18432 / 4;
        const float* B3s = As + 36864 / 4;
        loadfrag(As, B1s, B3s, 0, 0);
#pragma unroll
        for (int kk = 0; kk < 4; kk++) {
            int cur = kk & 1;
            if (kk < 3) loadfrag(As, B1s, B3s, kk + 1, cur ^ 1);
#pragma unroll
            for (int ni = 0; ni < 4; ni++) {
#pragma unroll
                for (int mi = 0; mi < 4; mi++)
                    mma_tf32(acc1[mi][ni], af[cur][mi], b1f[cur][ni][0], b1f[cur][ni][1]);
#pragma unroll
                for (int mi = 0; mi < 4; mi++)
                    mma_tf32(acc2[mi][ni], af[cur][mi], b3f[cur][ni][0], b3f[cur][ni][1]);
            }
        }
    }

    float* H = g_h + (size_t)z * CAP * DFF;
#pragma unroll
    for (int mi = 0; mi < 4; mi++)
#pragma unroll
        for (int half = 0; half < 2; half++) {
            int m = m0 + wm * 64 + mi * 16 + half * 8 + g;
            if (m < rows) {
#pragma unroll
                for (int ni = 0; ni < 4; ni++) {
                    float v0 = acc1[mi][ni][half * 2 + 0];
                    float v1 = acc1[mi][ni][half * 2 + 1];
                    float o0 = tf32f((v0 / (1.f + expf(-v0))) * acc2[mi][ni][half * 2 + 0]);
                    float o1 = tf32f((v1 / (1.f + expf(-v1))) * acc2[mi][ni][half * 2 + 1]);
                    int col = n0 + wn * 32 + ni * 8 + 2 * tg;
                    *(float2*)&H[(size_t)m * DFF + col] = make_float2(o0, o1);
                }
            }
        }
}

// ---------------- 5. gemm2: 128M x 256N, warp 64x64, 4-stage, 1 barrier/chunk ----------------
__global__ __launch_bounds__(256) void gemm2_mma(const float* __restrict__ W2) {
    int z = blockIdx.z, e = z & (NE - 1);
    int rows = g_cnt[z]; if (rows > CAP) rows = CAP;
    int m0 = blockIdx.y * 128; if (m0 >= rows) return;
    int n0 = blockIdx.x * 256;

    extern __shared__ char dsm[];
    uint32_t sb = smem_u32(dsm);

    const float* gA = g_h + (size_t)z * CAP * DFF + (size_t)m0 * DFF;
    const float* gB = W2  + (size_t)e * DM * DFF + (size_t)n0 * DFF;

    int tid = threadIdx.x, wid = tid >> 5, lane = tid & 31;
    int wm = wid >> 2, wn = wid & 3;
    int g = lane >> 2, tg = lane & 3;

    auto issue = [&](int c) {
        uint32_t st = sb + (uint32_t)(c % NSTAGE) * SSTAGE;
        int k0 = c * 32;
#pragma unroll
        for (int i = 0; i < 4; i++) {
            int f = tid + i * 256, r = f >> 3, c4 = f & 7;
            cp16(st + r * SROWB + c4 * 16, gA + (size_t)r * DFF + k0 + c4 * 4);
        }
#pragma unroll
        for (int i = 0; i < 8; i++) {
            int f = tid + i * 256, r = f >> 3, c4 = f & 7;
            cp16(st + 18432u + r * SROWB + c4 * 16, gB + (size_t)r * DFF + k0 + c4 * 4);
        }
    };

    float acc[4][8][4];
#pragma unroll
    for (int mi = 0; mi < 4; mi++)
#pragma unroll
        for (int ni = 0; ni < 8; ni++)
#pragma unroll
            for (int r = 0; r < 4; r++) acc[mi][ni][r] = 0.f;

    uint32_t af[2][4][4], bf[2][8][2];

    auto loadfrag = [&](const float* As, const float* Bs, int kk, int buf) {
        int k = kk * 8;
#pragma unroll
        for (int mi = 0; mi < 4; mi++) {
            int mb = wm * 64 + mi * 16;
            af[buf][mi][0] = __float_as_uint(As[(mb + g) * PAD + k + tg]);
            af[buf][mi][1] = __float_as_uint(As[(mb + 8 + g) * PAD + k + tg]);
            af[buf][mi][2] = __float_as_uint(As[(mb + g) * PAD + k + 4 + tg]);
            af[buf][mi][3] = __float_as_uint(As[(mb + 8 + g) * PAD + k + 4 + tg]);
        }
#pragma unroll
        for (int ni = 0; ni < 8; ni++) {
            int nb = wn * 64 + ni * 8;
            bf[buf][ni][0] = __float_as_uint(Bs[(nb + g) * PAD + k + tg]);
            bf[buf][ni][1] = __float_as_uint(Bs[(nb + g) * PAD + k + 4 + tg]);
        }
    };

    const int NC = DFF / 32;  // 128
    issue(0); CP_COMMIT();
    issue(1); CP_COMMIT();
    issue(2); CP_COMMIT();

    for (int c = 0; c < NC; c++) {
        CP_WAIT2();
        __syncthreads();
        if (c + 3 < NC) issue(c + 3);
        CP_COMMIT();
        const float* As = (const float*)(dsm + (c % NSTAGE) * SSTAGE);
        const float* Bs = As + 18432 / 4;
        loadfrag(As, Bs, 0, 0);
#pragma unroll
        for (int kk = 0; kk < 4; kk++) {
            int cur = kk & 1;
            if (kk < 3) loadfrag(As, Bs, kk + 1, cur ^ 1);
#pragma unroll
            for (int ni = 0; ni < 8; ni++)
#pragma unroll
                for (int mi = 0; mi < 4; mi++)
                    mma_tf32(acc[mi][ni], af[cur][mi], bf[cur][ni][0], bf[cur][ni][1]);
        }
    }

    float* O = g_ob + (size_t)z * CAP * DM;
#pragma unroll
    for (int mi = 0; mi < 4; mi++)
#pragma unroll
        for (int half = 0; half < 2; half++) {
            int m = m0 + wm * 64 + mi * 16 + half * 8 + g;
            if (m < rows) {
#pragma unroll
                for (int ni = 0; ni < 8; ni++) {
                    int col = n0 + wn * 64 + ni * 8 + 2 * tg;
                    *(float2*)&O[(size_t)m * DM + col] =
                        make_float2(acc[mi][ni][half * 2 + 0], acc[mi][ni][half * 2 + 1]);
                }
            }
        }
}

// ---------------- 6. weighted scatter/combine ----------------
__global__ __launch_bounds__(256) void scatter_kernel(float* __restrict__ out) {
    int t = blockIdx.x;
    int d4 = threadIdx.x;
    float4 acc = {0.f, 0.f, 0.f, 0.f};
#pragma unroll
    for (int k = 0; k < TOPK; k++) {
        int tk = t * 2 + k;
        int pos = g_pos[tk];
        if (pos < CAP) {
            int e = g_top_idx[tk];
            float w = g_top_w[tk];
            float4 v = ((const float4*)(g_ob + ((size_t)(k * NE + e) * CAP + pos) * DM))[d4];
            acc.x += v.x * w; acc.y += v.y * w; acc.z += v.z * w; acc.w += v.w * w;
        }
    }
    ((float4*)(out + (size_t)t * DM))[d4] = acc;
}

// ---------------- 7. aux loss ----------------
__global__ __launch_bounds__(256) void aux_kernel(float* __restrict__ out, int out_size) {
    __shared__ float red[256];
    __shared__ float Ps[NE];
    int tid = threadIdx.x;
    float loc[NE];
#pragma unroll
    for (int e = 0; e < NE; e++) loc[e] = 0.f;
    for (int i = tid; i < N_TOK; i += 256) {
#pragma unroll
        for (int e = 0; e < NE; e++) loc[e] += g_probs[i * NE + e];
    }
    for (int e = 0; e < NE; e++) {
        red[tid] = loc[e];
        __syncthreads();
        for (int s = 128; s > 0; s >>= 1) {
            if (tid < s) red[tid] += red[tid + s];
            __syncthreads();
        }
        if (tid == 0) Ps[e] = red[0];
        __syncthreads();
    }
    if (tid == 0) {
        float aux = 0.f;
        for (int e = 0; e < NE; e++) {
            float f = (float)(g_cnt[e] + g_cnt[NE + e]) / (float)(N_TOK * TOPK);
            float P = Ps[e] / (float)N_TOK;
            aux += f * P;
        }
        out[out_size - 1] = aux * (float)NE;
    }
}

// ---------------- launch ----------------
extern "C" void kernel_launch(void* const* d_in, const int* in_sizes, int n_in,
                              void* d_out, int out_size) {
    const float* x  = (const float*)d_in[0];
    const float* gw = (const float*)d_in[1];
    const float* w1 = (const float*)d_in[2];
    const float* w2 = (const float*)d_in[3];
    const float* w3 = (const float*)d_in[4];
    float* out = (float*)d_out;

    const int SMEM = NSTAGE * SSTAGE;   // 221184
    cudaFuncSetAttribute(gemm13_mma, cudaFuncAttributeMaxDynamicSharedMemorySize, SMEM);
    cudaFuncSetAttribute(gemm2_mma,  cudaFuncAttributeMaxDynamicSharedMemorySize, SMEM);

    float* w1t; cudaGetSymbolAddress((void**)&w1t, g_w1t);
    float* w3t; cudaGetSymbolAddress((void**)&w3t, g_w3t);
    float* w2t; cudaGetSymbolAddress((void**)&w2t, g_w2t);

    const int N4 = NE * DFF * DM / 4;
    const int CVT_GRID = (N4 + 255) / 256;

    // Side stream for the weight-convert chain (independent of router/scan/gather).
    // Event edges make this capture-legal: they become graph dependencies.
    cudaStream_t s2 = 0;
    cudaEvent_t evA = 0, evB = 0, evC = 0;
    bool ok =
        cudaStreamCreateWithFlags(&s2, cudaStreamNonBlocking) == cudaSuccess &&
        cudaEventCreateWithFlags(&evA, cudaEventDisableTiming) == cudaSuccess &&
        cudaEventCreateWithFlags(&evB, cudaEventDisableTiming) == cudaSuccess &&
        cudaEventCreateWithFlags(&evC, cudaEventDisableTiming) == cudaSuccess;
    // NOTE: objects are intentionally not destroyed — destroying a stream/event
    // participating in an active stream capture is illegal, and kernel_launch is
    // invoked only a handful of times (correctness + capture).

    if (ok) {
        // fork: s2 depends on stream-0 head
        cudaEventRecord(evA, 0);
        cudaStreamWaitEvent(s2, evA, 0);

        // s2: weight converts
        cvt_kernel<<<CVT_GRID, 256, 0, s2>>>((const float4*)w1, (float4*)w1t, N4);
        cvt_kernel<<<CVT_GRID, 256, 0, s2>>>((const float4*)w3, (float4*)w3t, N4);
        cudaEventRecord(evB, s2);                     // w1/w3 ready
        cvt_kernel<<<CVT_GRID, 256, 0, s2>>>((const float4*)w2, (float4*)w2t, N4);
        cudaEventRecord(evC, s2);                     // w2 ready

        // main: routing pipeline (concurrent with converts)
        router_kernel<<<N_TOK / 8, 256>>>(x, gw);
        scan_kernel<<<2, 256>>>();
        gather_kernel<<<N_TOK * TOPK, 256>>>(x);

        cudaStreamWaitEvent(0, evB, 0);               // join w1/w3
        dim3 g1(DFF / 128, CAP / 128, TOPK * NE);
        gemm13_mma<<<g1, 256, SMEM>>>(w1t, w3t);      // w2 cvt overlaps this

        cudaStreamWaitEvent(0, evC, 0);               // join w2
        dim3 g2(DM / 256, CAP / 128, TOPK * NE);
        gemm2_mma<<<g2, 256, SMEM>>>(w2t);

        scatter_kernel<<<N_TOK, 256>>>(out);
        aux_kernel<<<1, 256>>>(out, out_size);
    } else {
        // serial fallback (identical semantics)
        cvt_kernel<<<CVT_GRID, 256>>>((const float4*)w1, (float4*)w1t, N4);
        cvt_kernel<<<CVT_GRID, 256>>>((const float4*)w3, (float4*)w3t, N4);
        cvt_kernel<<<CVT_GRID, 256>>>((const float4*)w2, (float4*)w2t, N4);
        router_kernel<<<N_TOK / 8, 256>>>(x, gw);
        scan_kernel<<<2, 256>>>();
        gather_kernel<<<N_TOK * TOPK, 256>>>(x);
        dim3 g1(DFF / 128, CAP / 128, TOPK * NE);
        gemm13_mma<<<g1, 256, SMEM>>>(w1t, w3t);
        dim3 g2(DM / 256, CAP / 128, TOPK * NE);
        gemm2_mma<<<g2, 256, SMEM>>>(w2t);
        scatter_kernel<<<N_TOK, 256>>>(out);
        aux_kernel<<<1, 256>>>(out, out_size);
    }
}

// round 10
// speedup vs baseline: 6.5152x; 1.8530x over previous
#include <cuda_runtime.h>
#include <cuda_fp16.h>
#include <math.h>
#include <stdint.h>

#define N_TOK 8192
#define DM    1024
#define DFF   4096
#define NE    8
#define TOPK  2
#define CAP   1280
#define SROWB 144         // smem row stride bytes (128 data + 16 pad)
#define SSTAGE 55296      // bytes per pipeline stage (384 rows x 144B)
#define NSTAGE 4

// ---------------- scratch ----------------
__device__ __half g_buf[2 * NE * CAP * DM];        // x fp16
__device__ __half g_h  [2 * NE * CAP * DFF];       // hidden fp16
__device__ float  g_ob [2 * NE * CAP * DM];        // expert out fp32
__device__ __half g_w1t[NE * DFF * DM];
__device__ __half g_w3t[NE * DFF * DM];
__device__ __half g_w2t[NE * DM * DFF];
__device__ float  g_probs[N_TOK * NE];
__device__ int    g_top_idx[N_TOK * TOPK];
__device__ float  g_top_w [N_TOK * TOPK];
__device__ int    g_pos   [N_TOK * TOPK];
__device__ int    g_cnt   [TOPK * NE];

// ---------------- helpers ----------------
__device__ __forceinline__ uint32_t smem_u32(const void* p) {
    uint32_t a;
    asm("{ .reg .u64 t; cvta.to.shared.u64 t, %1; cvt.u32.u64 %0, t; }" : "=r"(a) : "l"(p));
    return a;
}
__device__ __forceinline__ void mma_f16(float* c, const uint32_t* a, uint32_t b0, uint32_t b1) {
    asm volatile(
        "mma.sync.aligned.m16n8k16.row.col.f32.f16.f16.f32 "
        "{%0,%1,%2,%3}, {%4,%5,%6,%7}, {%8,%9}, {%0,%1,%2,%3};"
        : "+f"(c[0]), "+f"(c[1]), "+f"(c[2]), "+f"(c[3])
        : "r"(a[0]), "r"(a[1]), "r"(a[2]), "r"(a[3]), "r"(b0), "r"(b1));
}
__device__ __forceinline__ void cp16(uint32_t s, const void* g) {
    asm volatile("cp.async.cg.shared.global [%0], [%1], 16;" :: "r"(s), "l"(g) : "memory");
}
#define CP_COMMIT() asm volatile("cp.async.commit_group;" ::: "memory")
#define CP_WAIT2()  asm volatile("cp.async.wait_group 2;" ::: "memory")

__device__ __forceinline__ uint32_t h2bits(float a, float b) {
    __half2 h = __floats2half2_rn(a, b);
    return *(uint32_t*)&h;
}

// ---------------- 0. weight convert (fp32 -> fp16) ----------------
__global__ __launch_bounds__(256) void cvt_kernel(const float4* __restrict__ src,
                                                  uint2* __restrict__ dst, int n4) {
    int i = blockIdx.x * blockDim.x + threadIdx.x;
    if (i < n4) {
        float4 v = src[i];
        uint2 o;
        o.x = h2bits(v.x, v.y);
        o.y = h2bits(v.z, v.w);
        dst[i] = o;
    }
}

// ---------------- 1. router ----------------
__global__ __launch_bounds__(256) void router_kernel(const float* __restrict__ x,
                                                     const float* __restrict__ gw) {
    int warp = (blockIdx.x * blockDim.x + threadIdx.x) >> 5;
    int lane = threadIdx.x & 31;
    if (warp >= N_TOK) return;
    const float* xr = x + (size_t)warp * DM;
    float acc[NE];
#pragma unroll
    for (int e = 0; e < NE; e++) acc[e] = 0.f;
    for (int i = lane; i < DM; i += 32) {
        float xv = xr[i];
#pragma unroll
        for (int e = 0; e < NE; e++) acc[e] += xv * gw[e * DM + i];
    }
#pragma unroll
    for (int off = 16; off > 0; off >>= 1)
#pragma unroll
        for (int e = 0; e < NE; e++) acc[e] += __shfl_xor_sync(0xffffffffu, acc[e], off);
    if (lane == 0) {
        float mx = acc[0];
#pragma unroll
        for (int e = 1; e < NE; e++) mx = fmaxf(mx, acc[e]);
        float p[NE], s = 0.f;
#pragma unroll
        for (int e = 0; e < NE; e++) { p[e] = expf(acc[e] - mx); s += p[e]; }
        float inv = 1.f / s;
        int i0 = 0;
#pragma unroll
        for (int e = 1; e < NE; e++) if (p[e] > p[i0]) i0 = e;
        int i1 = (i0 == 0) ? 1 : 0;
#pragma unroll
        for (int e = 0; e < NE; e++) if (e != i0 && e != i1 && p[e] > p[i1]) i1 = e;
#pragma unroll
        for (int e = 0; e < NE; e++) g_probs[warp * NE + e] = p[e] * inv;
        float p0 = p[i0] * inv, p1 = p[i1] * inv;
        float ws = p0 + p1 + 1e-10f;
        g_top_idx[warp * 2 + 0] = i0;  g_top_w[warp * 2 + 0] = p0 / ws;
        g_top_idx[warp * 2 + 1] = i1;  g_top_w[warp * 2 + 1] = p1 / ws;
    }
}

// ---------------- 2. capacity scan ----------------
__global__ __launch_bounds__(256) void scan_kernel() {
    int k = blockIdx.x;
    int t = threadIdx.x;
    const int CH = N_TOK / 256;
    __shared__ int cnt[256][NE];
    int local[NE];
#pragma unroll
    for (int e = 0; e < NE; e++) local[e] = 0;
    for (int i = 0; i < CH; i++) local[g_top_idx[(t * CH + i) * 2 + k]]++;
#pragma unroll
    for (int e = 0; e < NE; e++) cnt[t][e] = local[e];
    __syncthreads();
    if (t < NE) {
        int run = 0;
        for (int i = 0; i < 256; i++) { int v = cnt[i][t]; cnt[i][t] = run; run += v; }
        g_cnt[k * NE + t] = run;
    }
    __syncthreads();
    int off[NE];
#pragma unroll
    for (int e = 0; e < NE; e++) off[e] = cnt[t][e];
    for (int i = 0; i < CH; i++) {
        int tk = (t * CH + i) * 2 + k;
        g_pos[tk] = off[g_top_idx[tk]]++;
    }
}

// ---------------- 3. gather (fp32 -> fp16 at write) ----------------
__global__ __launch_bounds__(256) void gather_kernel(const float* __restrict__ x) {
    int tk = blockIdx.x;
    int pos = g_pos[tk];
    if (pos >= CAP) return;
    int e = g_top_idx[tk];
    int k = tk & 1, t = tk >> 1;
    float4 v = ((const float4*)(x + (size_t)t * DM))[threadIdx.x];
    uint2 o;
    o.x = h2bits(v.x, v.y);
    o.y = h2bits(v.z, v.w);
    uint2* dst = (uint2*)(g_buf + ((size_t)(k * NE + e) * CAP + pos) * DM);
    dst[threadIdx.x] = o;
}

// ---------------- 4. gemm13 fp16: 128M x 128N(x2), warp 64x32(x2), K-chunk 64, 4-stage ----------------
__global__ __launch_bounds__(256) void gemm13_mma(const __half* __restrict__ W1,
                                                  const __half* __restrict__ W3) {
    int z = blockIdx.z, e = z & (NE - 1);
    int rows = g_cnt[z]; if (rows > CAP) rows = CAP;
    int m0 = blockIdx.y * 128; if (m0 >= rows) return;
    int n0 = blockIdx.x * 128;

    extern __shared__ char dsm[];
    uint32_t sb = smem_u32(dsm);

    const char* gA  = (const char*)(g_buf + (size_t)z * CAP * DM + (size_t)m0 * DM);
    const char* gB1 = (const char*)(W1 + (size_t)e * DFF * DM + (size_t)n0 * DM);
    const char* gB3 = (const char*)(W3 + (size_t)e * DFF * DM + (size_t)n0 * DM);
    const int GR = DM * 2;   // global row bytes

    int tid = threadIdx.x, wid = tid >> 5, lane = tid & 31;
    int wm = wid >> 2, wn = wid & 3;
    int g = lane >> 2, tg = lane & 3;

    auto issue = [&](int c) {
        uint32_t st = sb + (uint32_t)(c % NSTAGE) * SSTAGE;
        int kb = c * 128;                // K-chunk 64 halves = 128 bytes
#pragma unroll
        for (int i = 0; i < 4; i++) {
            int f = tid + i * 256, r = f >> 3, c4 = f & 7;
            cp16(st + r * SROWB + c4 * 16, gA + (size_t)r * GR + kb + c4 * 16);
        }
#pragma unroll
        for (int i = 0; i < 4; i++) {
            int f = tid + i * 256, r = f >> 3, c4 = f & 7;
            cp16(st + 18432u + r * SROWB + c4 * 16, gB1 + (size_t)r * GR + kb + c4 * 16);
        }
#pragma unroll
        for (int i = 0; i < 4; i++) {
            int f = tid + i * 256, r = f >> 3, c4 = f & 7;
            cp16(st + 36864u + r * SROWB + c4 * 16, gB3 + (size_t)r * GR + kb + c4 * 16);
        }
    };

    float acc1[4][4][4], acc2[4][4][4];
#pragma unroll
    for (int mi = 0; mi < 4; mi++)
#pragma unroll
        for (int ni = 0; ni < 4; ni++)
#pragma unroll
            for (int r = 0; r < 4; r++) { acc1[mi][ni][r] = 0.f; acc2[mi][ni][r] = 0.f; }

    uint32_t af[2][4][4], b1f[2][4][2], b3f[2][4][2];

    auto loadfrag = [&](const char* st, int kk, int buf) {
        int ko = kk * 32 + 4 * tg;       // k16 step = 32 bytes
#pragma unroll
        for (int mi = 0; mi < 4; mi++) {
            int rb = (wm * 64 + mi * 16 + g) * SROWB;
            af[buf][mi][0] = *(const uint32_t*)(st + rb + ko);
            af[buf][mi][1] = *(const uint32_t*)(st + rb + 8 * SROWB + ko);
            af[buf][mi][2] = *(const uint32_t*)(st + rb + ko + 16);
            af[buf][mi][3] = *(const uint32_t*)(st + rb + 8 * SROWB + ko + 16);
        }
#pragma unroll
        for (int ni = 0; ni < 4; ni++) {
            int rn = (wn * 32 + ni * 8 + g) * SROWB;
            b1f[buf][ni][0] = *(const uint32_t*)(st + 18432 + rn + ko);
            b1f[buf][ni][1] = *(const uint32_t*)(st + 18432 + rn + ko + 16);
            b3f[buf][ni][0] = *(const uint32_t*)(st + 36864 + rn + ko);
            b3f[buf][ni][1] = *(const uint32_t*)(st + 36864 + rn + ko + 16);
        }
    };

    const int NC = DM / 64;   // 16
    issue(0); CP_COMMIT();
    issue(1); CP_COMMIT();
    issue(2); CP_COMMIT();

    for (int c = 0; c < NC; c++) {
        CP_WAIT2();
        __syncthreads();
        if (c + 3 < NC) issue(c + 3);
        CP_COMMIT();
        const char* st = dsm + (c % NSTAGE) * SSTAGE;
        loadfrag(st, 0, 0);
#pragma unroll
        for (int kk = 0; kk < 4; kk++) {
            int cur = kk & 1;
            if (kk < 3) loadfrag(st, kk + 1, cur ^ 1);
#pragma unroll
            for (int ni = 0; ni < 4; ni++) {
#pragma unroll
                for (int mi = 0; mi < 4; mi++)
                    mma_f16(acc1[mi][ni], af[cur][mi], b1f[cur][ni][0], b1f[cur][ni][1]);
#pragma unroll
                for (int mi = 0; mi < 4; mi++)
                    mma_f16(acc2[mi][ni], af[cur][mi], b3f[cur][ni][0], b3f[cur][ni][1]);
            }
        }
    }

    __half* H = g_h + (size_t)z * CAP * DFF;
#pragma unroll
    for (int mi = 0; mi < 4; mi++)
#pragma unroll
        for (int half = 0; half < 2; half++) {
            int m = m0 + wm * 64 + mi * 16 + half * 8 + g;
            if (m < rows) {
#pragma unroll
                for (int ni = 0; ni < 4; ni++) {
                    float v0 = acc1[mi][ni][half * 2 + 0];
                    float v1 = acc1[mi][ni][half * 2 + 1];
                    float o0 = (v0 / (1.f + expf(-v0))) * acc2[mi][ni][half * 2 + 0];
                    float o1 = (v1 / (1.f + expf(-v1))) * acc2[mi][ni][half * 2 + 1];
                    int col = n0 + wn * 32 + ni * 8 + 2 * tg;
                    __half2 hv = __floats2half2_rn(o0, o1);
                    *(__half2*)&H[(size_t)m * DFF + col] = hv;
                }
            }
        }
}

// ---------------- 5. gemm2 fp16: 128M x 256N, warp 64x64, K-chunk 64, 4-stage ----------------
__global__ __launch_bounds__(256) void gemm2_mma(const __half* __restrict__ W2) {
    int z = blockIdx.z, e = z & (NE - 1);
    int rows = g_cnt[z]; if (rows > CAP) rows = CAP;
    int m0 = blockIdx.y * 128; if (m0 >= rows) return;
    int n0 = blockIdx.x * 256;

    extern __shared__ char dsm[];
    uint32_t sb = smem_u32(dsm);

    const char* gA = (const char*)(g_h + (size_t)z * CAP * DFF + (size_t)m0 * DFF);
    const char* gB = (const char*)(W2 + (size_t)e * DM * DFF + (size_t)n0 * DFF);
    const int GR = DFF * 2;

    int tid = threadIdx.x, wid = tid >> 5, lane = tid & 31;
    int wm = wid >> 2, wn = wid & 3;
    int g = lane >> 2, tg = lane & 3;

    auto issue = [&](int c) {
        uint32_t st = sb + (uint32_t)(c % NSTAGE) * SSTAGE;
        int kb = c * 128;
#pragma unroll
        for (int i = 0; i < 4; i++) {
            int f = tid + i * 256, r = f >> 3, c4 = f & 7;
            cp16(st + r * SROWB + c4 * 16, gA + (size_t)r * GR + kb + c4 * 16);
        }
#pragma unroll
        for (int i = 0; i < 8; i++) {
            int f = tid + i * 256, r = f >> 3, c4 = f & 7;
            cp16(st + 18432u + r * SROWB + c4 * 16, gB + (size_t)r * GR + kb + c4 * 16);
        }
    };

    float acc[4][8][4];
#pragma unroll
    for (int mi = 0; mi < 4; mi++)
#pragma unroll
        for (int ni = 0; ni < 8; ni++)
#pragma unroll
            for (int r = 0; r < 4; r++) acc[mi][ni][r] = 0.f;

    uint32_t af[2][4][4], bf[2][8][2];

    auto loadfrag = [&](const char* st, int kk, int buf) {
        int ko = kk * 32 + 4 * tg;
#pragma unroll
        for (int mi = 0; mi < 4; mi++) {
            int rb = (wm * 64 + mi * 16 + g) * SROWB;
            af[buf][mi][0] = *(const uint32_t*)(st + rb + ko);
            af[buf][mi][1] = *(const uint32_t*)(st + rb + 8 * SROWB + ko);
            af[buf][mi][2] = *(const uint32_t*)(st + rb + ko + 16);
            af[buf][mi][3] = *(const uint32_t*)(st + rb + 8 * SROWB + ko + 16);
        }
#pragma unroll
        for (int ni = 0; ni < 8; ni++) {
            int rn = (wn * 64 + ni * 8 + g) * SROWB;
            bf[buf][ni][0] = *(const uint32_t*)(st + 18432 + rn + ko);
            bf[buf][ni][1] = *(const uint32_t*)(st + 18432 + rn + ko + 16);
        }
    };

    const int NC = DFF / 64;  // 64
    issue(0); CP_COMMIT();
    issue(1); CP_COMMIT();
    issue(2); CP_COMMIT();

    for (int c = 0; c < NC; c++) {
        CP_WAIT2();
        __syncthreads();
        if (c + 3 < NC) issue(c + 3);
        CP_COMMIT();
        const char* st = dsm + (c % NSTAGE) * SSTAGE;
        loadfrag(st, 0, 0);
#pragma unroll
        for (int kk = 0; kk < 4; kk++) {
            int cur = kk & 1;
            if (kk < 3) loadfrag(st, kk + 1, cur ^ 1);
#pragma unroll
            for (int ni = 0; ni < 8; ni++)
#pragma unroll
                for (int mi = 0; mi < 4; mi++)
                    mma_f16(acc[mi][ni], af[cur][mi], bf[cur][ni][0], bf[cur][ni][1]);
        }
    }

    float* O = g_ob + (size_t)z * CAP * DM;
#pragma unroll
    for (int mi = 0; mi < 4; mi++)
#pragma unroll
        for (int half = 0; half < 2; half++) {
            int m = m0 + wm * 64 + mi * 16 + half * 8 + g;
            if (m < rows) {
#pragma unroll
                for (int ni = 0; ni < 8; ni++) {
                    int col = n0 + wn * 64 + ni * 8 + 2 * tg;
                    *(float2*)&O[(size_t)m * DM + col] =
                        make_float2(acc[mi][ni][half * 2 + 0], acc[mi][ni][half * 2 + 1]);
                }
            }
        }
}

// ---------------- 6. weighted scatter/combine ----------------
__global__ __launch_bounds__(256) void scatter_kernel(float* __restrict__ out) {
    int t = blockIdx.x;
    int d4 = threadIdx.x;
    float4 acc = {0.f, 0.f, 0.f, 0.f};
#pragma unroll
    for (int k = 0; k < TOPK; k++) {
        int tk = t * 2 + k;
        int pos = g_pos[tk];
        if (pos < CAP) {
            int e = g_top_idx[tk];
            float w = g_top_w[tk];
            float4 v = ((const float4*)(g_ob + ((size_t)(k * NE + e) * CAP + pos) * DM))[d4];
            acc.x += v.x * w; acc.y += v.y * w; acc.z += v.z * w; acc.w += v.w * w;
        }
    }
    ((float4*)(out + (size_t)t * DM))[d4] = acc;
}

// ---------------- 7. aux loss ----------------
__global__ __launch_bounds__(256) void aux_kernel(float* __restrict__ out, int out_size) {
    __shared__ float red[256];
    __shared__ float Ps[NE];
    int tid = threadIdx.x;
    float loc[NE];
#pragma unroll
    for (int e = 0; e < NE; e++) loc[e] = 0.f;
    for (int i = tid; i < N_TOK; i += 256) {
#pragma unroll
        for (int e = 0; e < NE; e++) loc[e] += g_probs[i * NE + e];
    }
    for (int e = 0; e < NE; e++) {
        red[tid] = loc[e];
        __syncthreads();
        for (int s = 128; s > 0; s >>= 1) {
            if (tid < s) red[tid] += red[tid + s];
            __syncthreads();
        }
        if (tid == 0) Ps[e] = red[0];
        __syncthreads();
    }
    if (tid == 0) {
        float aux = 0.f;
        for (int e = 0; e < NE; e++) {
            float f = (float)(g_cnt[e] + g_cnt[NE + e]) / (float)(N_TOK * TOPK);
            float P = Ps[e] / (float)N_TOK;
            aux += f * P;
        }
        out[out_size - 1] = aux * (float)NE;
    }
}

// ---------------- launch ----------------
extern "C" void kernel_launch(void* const* d_in, const int* in_sizes, int n_in,
                              void* d_out, int out_size) {
    const float* x  = (const float*)d_in[0];
    const float* gw = (const float*)d_in[1];
    const float* w1 = (const float*)d_in[2];
    const float* w2 = (const float*)d_in[3];
    const float* w3 = (const float*)d_in[4];
    float* out = (float*)d_out;

    const int SMEM = NSTAGE * SSTAGE;   // 221184
    cudaFuncSetAttribute(gemm13_mma, cudaFuncAttributeMaxDynamicSharedMemorySize, SMEM);
    cudaFuncSetAttribute(gemm2_mma,  cudaFuncAttributeMaxDynamicSharedMemorySize, SMEM);

    __half* w1t; cudaGetSymbolAddress((void**)&w1t, g_w1t);
    __half* w3t; cudaGetSymbolAddress((void**)&w3t, g_w3t);
    __half* w2t; cudaGetSymbolAddress((void**)&w2t, g_w2t);

    const int N4 = NE * DFF * DM / 4;
    const int CVT_GRID = (N4 + 255) / 256;

    cudaStream_t s2 = 0;
    cudaEvent_t evA = 0, evB = 0, evC = 0;
    bool ok =
        cudaStreamCreateWithFlags(&s2, cudaStreamNonBlocking) == cudaSuccess &&
        cudaEventCreateWithFlags(&evA, cudaEventDisableTiming) == cudaSuccess &&
        cudaEventCreateWithFlags(&evB, cudaEventDisableTiming) == cudaSuccess &&
        cudaEventCreateWithFlags(&evC, cudaEventDisableTiming) == cudaSuccess;
    // objects intentionally leaked: destroying them during active capture is illegal,
    // and kernel_launch runs only a handful of times.

    if (ok) {
        cudaEventRecord(evA, 0);
        cudaStreamWaitEvent(s2, evA, 0);

        cvt_kernel<<<CVT_GRID, 256, 0, s2>>>((const float4*)w1, (uint2*)w1t, N4);
        cvt_kernel<<<CVT_GRID, 256, 0, s2>>>((const float4*)w3, (uint2*)w3t, N4);
        cudaEventRecord(evB, s2);
        cvt_kernel<<<CVT_GRID, 256, 0, s2>>>((const float4*)w2, (uint2*)w2t, N4);
        cudaEventRecord(evC, s2);

        router_kernel<<<N_TOK / 8, 256>>>(x, gw);
        scan_kernel<<<2, 256>>>();
        gather_kernel<<<N_TOK * TOPK, 256>>>(x);

        cudaStreamWaitEvent(0, evB, 0);
        dim3 g1(DFF / 128, CAP / 128, TOPK * NE);
        gemm13_mma<<<g1, 256, SMEM>>>(w1t, w3t);

        cudaStreamWaitEvent(0, evC, 0);
        dim3 g2(DM / 256, CAP / 128, TOPK * NE);
        gemm2_mma<<<g2, 256, SMEM>>>(w2t);

        scatter_kernel<<<N_TOK, 256>>>(out);
        aux_kernel<<<1, 256>>>(out, out_size);
    } else {
        cvt_kernel<<<CVT_GRID, 256>>>((const float4*)w1, (uint2*)w1t, N4);
        cvt_kernel<<<CVT_GRID, 256>>>((const float4*)w3, (uint2*)w3t, N4);
        cvt_kernel<<<CVT_GRID, 256>>>((const float4*)w2, (uint2*)w2t, N4);
        router_kernel<<<N_TOK / 8, 256>>>(x, gw);
        scan_kernel<<<2, 256>>>();
        gather_kernel<<<N_TOK * TOPK, 256>>>(x);
        dim3 g1(DFF / 128, CAP / 128, TOPK * NE);
        gemm13_mma<<<g1, 256, SMEM>>>(w1t, w3t);
        dim3 g2(DM / 256, CAP / 128, TOPK * NE);
        gemm2_mma<<<g2, 256, SMEM>>>(w2t);
        scatter_kernel<<<N_TOK, 256>>>(out);
        aux_kernel<<<1, 256>>>(out, out_size);
    }
}

// round 11
// speedup vs baseline: 6.6985x; 1.0281x over previous
#include <cuda_runtime.h>
#include <cuda_fp16.h>
#include <math.h>
#include <stdint.h>

#define N_TOK 8192
#define DM    1024
#define DFF   4096
#define NE    8
#define TOPK  2
#define CAP   1280
#define SROWB 144         // smem row stride bytes (128 data + 16 pad)
#define SSTAGE 55296      // bytes per pipeline stage (384 rows x 144B)
#define NSTAGE 4

// ---------------- scratch ----------------
__device__ __half g_buf[2 * NE * CAP * DM];
__device__ __half g_h  [2 * NE * CAP * DFF];
__device__ float  g_ob [2 * NE * CAP * DM];
__device__ __half g_w1t[NE * DFF * DM];
__device__ __half g_w3t[NE * DFF * DM];
__device__ __half g_w2t[NE * DM * DFF];
__device__ float  g_probs[N_TOK * NE];
__device__ int    g_top_idx[N_TOK * TOPK];
__device__ float  g_top_w [N_TOK * TOPK];
__device__ int    g_pos   [N_TOK * TOPK];
__device__ int    g_cnt   [TOPK * NE];

// ---------------- helpers ----------------
__device__ __forceinline__ uint32_t smem_u32(const void* p) {
    uint32_t a;
    asm("{ .reg .u64 t; cvta.to.shared.u64 t, %1; cvt.u32.u64 %0, t; }" : "=r"(a) : "l"(p));
    return a;
}
__device__ __forceinline__ void mma_f16(float* c, const uint32_t* a, uint32_t b0, uint32_t b1) {
    asm volatile(
        "mma.sync.aligned.m16n8k16.row.col.f32.f16.f16.f32 "
        "{%0,%1,%2,%3}, {%4,%5,%6,%7}, {%8,%9}, {%0,%1,%2,%3};"
        : "+f"(c[0]), "+f"(c[1]), "+f"(c[2]), "+f"(c[3])
        : "r"(a[0]), "r"(a[1]), "r"(a[2]), "r"(a[3]), "r"(b0), "r"(b1));
}
__device__ __forceinline__ void ldsm_x4(uint32_t& r0, uint32_t& r1, uint32_t& r2, uint32_t& r3,
                                        uint32_t addr) {
    asm volatile("ldmatrix.sync.aligned.m8n8.x4.shared.b16 {%0,%1,%2,%3}, [%4];"
                 : "=r"(r0), "=r"(r1), "=r"(r2), "=r"(r3) : "r"(addr));
}
__device__ __forceinline__ void cp16(uint32_t s, const void* g) {
    asm volatile("cp.async.cg.shared.global [%0], [%1], 16;" :: "r"(s), "l"(g) : "memory");
}
#define CP_COMMIT() asm volatile("cp.async.commit_group;" ::: "memory")
#define CP_WAIT2()  asm volatile("cp.async.wait_group 2;" ::: "memory")

__device__ __forceinline__ uint32_t h2bits(float a, float b) {
    __half2 h = __floats2half2_rn(a, b);
    return *(uint32_t*)&h;
}

// ---------------- 0. weight convert (fp32 -> fp16) ----------------
__global__ __launch_bounds__(256) void cvt_kernel(const float4* __restrict__ src,
                                                  uint2* __restrict__ dst, int n4) {
    int i = blockIdx.x * blockDim.x + threadIdx.x;
    if (i < n4) {
        float4 v = src[i];
        uint2 o;
        o.x = h2bits(v.x, v.y);
        o.y = h2bits(v.z, v.w);
        dst[i] = o;
    }
}

// ---------------- 1. router ----------------
__global__ __launch_bounds__(256) void router_kernel(const float* __restrict__ x,
                                                     const float* __restrict__ gw) {
    int warp = (blockIdx.x * blockDim.x + threadIdx.x) >> 5;
    int lane = threadIdx.x & 31;
    if (warp >= N_TOK) return;
    const float* xr = x + (size_t)warp * DM;
    float acc[NE];
#pragma unroll
    for (int e = 0; e < NE; e++) acc[e] = 0.f;
    for (int i = lane; i < DM; i += 32) {
        float xv = xr[i];
#pragma unroll
        for (int e = 0; e < NE; e++) acc[e] += xv * gw[e * DM + i];
    }
#pragma unroll
    for (int off = 16; off > 0; off >>= 1)
#pragma unroll
        for (int e = 0; e < NE; e++) acc[e] += __shfl_xor_sync(0xffffffffu, acc[e], off);
    if (lane == 0) {
        float mx = acc[0];
#pragma unroll
        for (int e = 1; e < NE; e++) mx = fmaxf(mx, acc[e]);
        float p[NE], s = 0.f;
#pragma unroll
        for (int e = 0; e < NE; e++) { p[e] = expf(acc[e] - mx); s += p[e]; }
        float inv = 1.f / s;
        int i0 = 0;
#pragma unroll
        for (int e = 1; e < NE; e++) if (p[e] > p[i0]) i0 = e;
        int i1 = (i0 == 0) ? 1 : 0;
#pragma unroll
        for (int e = 0; e < NE; e++) if (e != i0 && e != i1 && p[e] > p[i1]) i1 = e;
#pragma unroll
        for (int e = 0; e < NE; e++) g_probs[warp * NE + e] = p[e] * inv;
        float p0 = p[i0] * inv, p1 = p[i1] * inv;
        float ws = p0 + p1 + 1e-10f;
        g_top_idx[warp * 2 + 0] = i0;  g_top_w[warp * 2 + 0] = p0 / ws;
        g_top_idx[warp * 2 + 1] = i1;  g_top_w[warp * 2 + 1] = p1 / ws;
    }
}

// ---------------- 2. capacity scan ----------------
__global__ __launch_bounds__(256) void scan_kernel() {
    int k = blockIdx.x;
    int t = threadIdx.x;
    const int CH = N_TOK / 256;
    __shared__ int cnt[256][NE];
    int local[NE];
#pragma unroll
    for (int e = 0; e < NE; e++) local[e] = 0;
    for (int i = 0; i < CH; i++) local[g_top_idx[(t * CH + i) * 2 + k]]++;
#pragma unroll
    for (int e = 0; e < NE; e++) cnt[t][e] = local[e];
    __syncthreads();
    if (t < NE) {
        int run = 0;
        for (int i = 0; i < 256; i++) { int v = cnt[i][t]; cnt[i][t] = run; run += v; }
        g_cnt[k * NE + t] = run;
    }
    __syncthreads();
    int off[NE];
#pragma unroll
    for (int e = 0; e < NE; e++) off[e] = cnt[t][e];
    for (int i = 0; i < CH; i++) {
        int tk = (t * CH + i) * 2 + k;
        g_pos[tk] = off[g_top_idx[tk]]++;
    }
}

// ---------------- 3. gather (fp32 -> fp16 at write) ----------------
__global__ __launch_bounds__(256) void gather_kernel(const float* __restrict__ x) {
    int tk = blockIdx.x;
    int pos = g_pos[tk];
    if (pos >= CAP) return;
    int e = g_top_idx[tk];
    int k = tk & 1, t = tk >> 1;
    float4 v = ((const float4*)(x + (size_t)t * DM))[threadIdx.x];
    uint2 o;
    o.x = h2bits(v.x, v.y);
    o.y = h2bits(v.z, v.w);
    uint2* dst = (uint2*)(g_buf + ((size_t)(k * NE + e) * CAP + pos) * DM);
    dst[threadIdx.x] = o;
}

// ---------------- 4. gemm13 fp16 + ldmatrix ----------------
__global__ __launch_bounds__(256) void gemm13_mma(const __half* __restrict__ W1,
                                                  const __half* __restrict__ W3) {
    int z = blockIdx.z, e = z & (NE - 1);
    int rows = g_cnt[z]; if (rows > CAP) rows = CAP;
    int m0 = blockIdx.y * 128; if (m0 >= rows) return;
    int n0 = blockIdx.x * 128;

    extern __shared__ char dsm[];
    uint32_t sb = smem_u32(dsm);

    const char* gA  = (const char*)(g_buf + (size_t)z * CAP * DM + (size_t)m0 * DM);
    const char* gB1 = (const char*)(W1 + (size_t)e * DFF * DM + (size_t)n0 * DM);
    const char* gB3 = (const char*)(W3 + (size_t)e * DFF * DM + (size_t)n0 * DM);
    const int GR = DM * 2;

    int tid = threadIdx.x, wid = tid >> 5, lane = tid & 31;
    int wm = wid >> 2, wn = wid & 3;
    int g = lane >> 2, tg = lane & 3;

    // ldmatrix per-lane row offsets
    uint32_t Aoff = (uint32_t)((wm * 64 + ((lane >> 3) & 1) * 8 + (lane & 7)) * SROWB
                               + (lane >> 4) * 16);
    uint32_t Boff = (uint32_t)(((lane >> 4) * 8 + (lane & 7)) * SROWB
                               + ((lane >> 3) & 1) * 16);

    auto issue = [&](int c) {
        uint32_t st = sb + (uint32_t)(c % NSTAGE) * SSTAGE;
        int kb = c * 128;
#pragma unroll
        for (int i = 0; i < 4; i++) {
            int f = tid + i * 256, r = f >> 3, c4 = f & 7;
            cp16(st + r * SROWB + c4 * 16, gA + (size_t)r * GR + kb + c4 * 16);
        }
#pragma unroll
        for (int i = 0; i < 4; i++) {
            int f = tid + i * 256, r = f >> 3, c4 = f & 7;
            cp16(st + 18432u + r * SROWB + c4 * 16, gB1 + (size_t)r * GR + kb + c4 * 16);
        }
#pragma unroll
        for (int i = 0; i < 4; i++) {
            int f = tid + i * 256, r = f >> 3, c4 = f & 7;
            cp16(st + 36864u + r * SROWB + c4 * 16, gB3 + (size_t)r * GR + kb + c4 * 16);
        }
    };

    float acc1[4][4][4], acc2[4][4][4];
#pragma unroll
    for (int mi = 0; mi < 4; mi++)
#pragma unroll
        for (int ni = 0; ni < 4; ni++)
#pragma unroll
            for (int r = 0; r < 4; r++) { acc1[mi][ni][r] = 0.f; acc2[mi][ni][r] = 0.f; }

    uint32_t af[2][4][4], b1f[2][4][2], b3f[2][4][2];

    auto loadfrag = [&](uint32_t stu, int kk, int buf) {
        uint32_t ka = stu + (uint32_t)(kk * 32);
#pragma unroll
        for (int mi = 0; mi < 4; mi++)
            ldsm_x4(af[buf][mi][0], af[buf][mi][1], af[buf][mi][2], af[buf][mi][3],
                    ka + Aoff + (uint32_t)(mi * 16 * SROWB));
#pragma unroll
        for (int np = 0; np < 2; np++) {
            uint32_t nboff = (uint32_t)((wn * 32 + np * 16) * SROWB);
            ldsm_x4(b1f[buf][2*np][0], b1f[buf][2*np][1], b1f[buf][2*np+1][0], b1f[buf][2*np+1][1],
                    ka + 18432u + Boff + nboff);
            ldsm_x4(b3f[buf][2*np][0], b3f[buf][2*np][1], b3f[buf][2*np+1][0], b3f[buf][2*np+1][1],
                    ka + 36864u + Boff + nboff);
        }
    };

    const int NC = DM / 64;   // 16
    issue(0); CP_COMMIT();
    issue(1); CP_COMMIT();
    issue(2); CP_COMMIT();

    for (int c = 0; c < NC; c++) {
        CP_WAIT2();
        __syncthreads();
        if (c + 3 < NC) issue(c + 3);
        CP_COMMIT();
        uint32_t stu = sb + (uint32_t)(c % NSTAGE) * SSTAGE;
        loadfrag(stu, 0, 0);
#pragma unroll
        for (int kk = 0; kk < 4; kk++) {
            int cur = kk & 1;
            if (kk < 3) loadfrag(stu, kk + 1, cur ^ 1);
#pragma unroll
            for (int ni = 0; ni < 4; ni++) {
#pragma unroll
                for (int mi = 0; mi < 4; mi++)
                    mma_f16(acc1[mi][ni], af[cur][mi], b1f[cur][ni][0], b1f[cur][ni][1]);
#pragma unroll
                for (int mi = 0; mi < 4; mi++)
                    mma_f16(acc2[mi][ni], af[cur][mi], b3f[cur][ni][0], b3f[cur][ni][1]);
            }
        }
    }

    __half* H = g_h + (size_t)z * CAP * DFF;
#pragma unroll
    for (int mi = 0; mi < 4; mi++)
#pragma unroll
        for (int half = 0; half < 2; half++) {
            int m = m0 + wm * 64 + mi * 16 + half * 8 + g;
            if (m < rows) {
#pragma unroll
                for (int ni = 0; ni < 4; ni++) {
                    float v0 = acc1[mi][ni][half * 2 + 0];
                    float v1 = acc1[mi][ni][half * 2 + 1];
                    float o0 = (v0 / (1.f + expf(-v0))) * acc2[mi][ni][half * 2 + 0];
                    float o1 = (v1 / (1.f + expf(-v1))) * acc2[mi][ni][half * 2 + 1];
                    int col = n0 + wn * 32 + ni * 8 + 2 * tg;
                    __half2 hv = __floats2half2_rn(o0, o1);
                    *(__half2*)&H[(size_t)m * DFF + col] = hv;
                }
            }
        }
}

// ---------------- 5. gemm2 fp16 + ldmatrix ----------------
__global__ __launch_bounds__(256) void gemm2_mma(const __half* __restrict__ W2) {
    int z = blockIdx.z, e = z & (NE - 1);
    int rows = g_cnt[z]; if (rows > CAP) rows = CAP;
    int m0 = blockIdx.y * 128; if (m0 >= rows) return;
    int n0 = blockIdx.x * 256;

    extern __shared__ char dsm[];
    uint32_t sb = smem_u32(dsm);

    const char* gA = (const char*)(g_h + (size_t)z * CAP * DFF + (size_t)m0 * DFF);
    const char* gB = (const char*)(W2 + (size_t)e * DM * DFF + (size_t)n0 * DFF);
    const int GR = DFF * 2;

    int tid = threadIdx.x, wid = tid >> 5, lane = tid & 31;
    int wm = wid >> 2, wn = wid & 3;
    int g = lane >> 2, tg = lane & 3;

    uint32_t Aoff = (uint32_t)((wm * 64 + ((lane >> 3) & 1) * 8 + (lane & 7)) * SROWB
                               + (lane >> 4) * 16);
    uint32_t Boff = (uint32_t)(((lane >> 4) * 8 + (lane & 7)) * SROWB
                               + ((lane >> 3) & 1) * 16);

    auto issue = [&](int c) {
        uint32_t st = sb + (uint32_t)(c % NSTAGE) * SSTAGE;
        int kb = c * 128;
#pragma unroll
        for (int i = 0; i < 4; i++) {
            int f = tid + i * 256, r = f >> 3, c4 = f & 7;
            cp16(st + r * SROWB + c4 * 16, gA + (size_t)r * GR + kb + c4 * 16);
        }
#pragma unroll
        for (int i = 0; i < 8; i++) {
            int f = tid + i * 256, r = f >> 3, c4 = f & 7;
            cp16(st + 18432u + r * SROWB + c4 * 16, gB + (size_t)r * GR + kb + c4 * 16);
        }
    };

    float acc[4][8][4];
#pragma unroll
    for (int mi = 0; mi < 4; mi++)
#pragma unroll
        for (int ni = 0; ni < 8; ni++)
#pragma unroll
            for (int r = 0; r < 4; r++) acc[mi][ni][r] = 0.f;

    uint32_t af[2][4][4], bf[2][8][2];

    auto loadfrag = [&](uint32_t stu, int kk, int buf) {
        uint32_t ka = stu + (uint32_t)(kk * 32);
#pragma unroll
        for (int mi = 0; mi < 4; mi++)
            ldsm_x4(af[buf][mi][0], af[buf][mi][1], af[buf][mi][2], af[buf][mi][3],
                    ka + Aoff + (uint32_t)(mi * 16 * SROWB));
#pragma unroll
        for (int np = 0; np < 4; np++) {
            uint32_t nboff = (uint32_t)((wn * 64 + np * 16) * SROWB);
            ldsm_x4(bf[buf][2*np][0], bf[buf][2*np][1], bf[buf][2*np+1][0], bf[buf][2*np+1][1],
                    ka + 18432u + Boff + nboff);
        }
    };

    const int NC = DFF / 64;  // 64
    issue(0); CP_COMMIT();
    issue(1); CP_COMMIT();
    issue(2); CP_COMMIT();

    for (int c = 0; c < NC; c++) {
        CP_WAIT2();
        __syncthreads();
        if (c + 3 < NC) issue(c + 3);
        CP_COMMIT();
        uint32_t stu = sb + (uint32_t)(c % NSTAGE) * SSTAGE;
        loadfrag(stu, 0, 0);
#pragma unroll
        for (int kk = 0; kk < 4; kk++) {
            int cur = kk & 1;
            if (kk < 3) loadfrag(stu, kk + 1, cur ^ 1);
#pragma unroll
            for (int ni = 0; ni < 8; ni++)
#pragma unroll
                for (int mi = 0; mi < 4; mi++)
                    mma_f16(acc[mi][ni], af[cur][mi], bf[cur][ni][0], bf[cur][ni][1]);
        }
    }

    float* O = g_ob + (size_t)z * CAP * DM;
#pragma unroll
    for (int mi = 0; mi < 4; mi++)
#pragma unroll
        for (int half = 0; half < 2; half++) {
            int m = m0 + wm * 64 + mi * 16 + half * 8 + g;
            if (m < rows) {
#pragma unroll
                for (int ni = 0; ni < 8; ni++) {
                    int col = n0 + wn * 64 + ni * 8 + 2 * tg;
                    *(float2*)&O[(size_t)m * DM + col] =
                        make_float2(acc[mi][ni][half * 2 + 0], acc[mi][ni][half * 2 + 1]);
                }
            }
        }
}

// ---------------- 6. weighted scatter/combine ----------------
__global__ __launch_bounds__(256) void scatter_kernel(float* __restrict__ out) {
    int t = blockIdx.x;
    int d4 = threadIdx.x;
    float4 acc = {0.f, 0.f, 0.f, 0.f};
#pragma unroll
    for (int k = 0; k < TOPK; k++) {
        int tk = t * 2 + k;
        int pos = g_pos[tk];
        if (pos < CAP) {
            int e = g_top_idx[tk];
            float w = g_top_w[tk];
            float4 v = ((const float4*)(g_ob + ((size_t)(k * NE + e) * CAP + pos) * DM))[d4];
            acc.x += v.x * w; acc.y += v.y * w; acc.z += v.z * w; acc.w += v.w * w;
        }
    }
    ((float4*)(out + (size_t)t * DM))[d4] = acc;
}

// ---------------- 7. aux loss ----------------
__global__ __launch_bounds__(256) void aux_kernel(float* __restrict__ out, int out_size) {
    __shared__ float red[256];
    __shared__ float Ps[NE];
    int tid = threadIdx.x;
    float loc[NE];
#pragma unroll
    for (int e = 0; e < NE; e++) loc[e] = 0.f;
    for (int i = tid; i < N_TOK; i += 256) {
#pragma unroll
        for (int e = 0; e < NE; e++) loc[e] += g_probs[i * NE + e];
    }
    for (int e = 0; e < NE; e++) {
        red[tid] = loc[e];
        __syncthreads();
        for (int s = 128; s > 0; s >>= 1) {
            if (tid < s) red[tid] += red[tid + s];
            __syncthreads();
        }
        if (tid == 0) Ps[e] = red[0];
        __syncthreads();
    }
    if (tid == 0) {
        float aux = 0.f;
        for (int e = 0; e < NE; e++) {
            float f = (float)(g_cnt[e] + g_cnt[NE + e]) / (float)(N_TOK * TOPK);
            float P = Ps[e] / (float)N_TOK;
            aux += f * P;
        }
        out[out_size - 1] = aux * (float)NE;
    }
}

// ---------------- launch ----------------
extern "C" void kernel_launch(void* const* d_in, const int* in_sizes, int n_in,
                              void* d_out, int out_size) {
    const float* x  = (const float*)d_in[0];
    const float* gw = (const float*)d_in[1];
    const float* w1 = (const float*)d_in[2];
    const float* w2 = (const float*)d_in[3];
    const float* w3 = (const float*)d_in[4];
    float* out = (float*)d_out;

    const int SMEM = NSTAGE * SSTAGE;   // 221184
    cudaFuncSetAttribute(gemm13_mma, cudaFuncAttributeMaxDynamicSharedMemorySize, SMEM);
    cudaFuncSetAttribute(gemm2_mma,  cudaFuncAttributeMaxDynamicSharedMemorySize, SMEM);

    __half* w1t; cudaGetSymbolAddress((void**)&w1t, g_w1t);
    __half* w3t; cudaGetSymbolAddress((void**)&w3t, g_w3t);
    __half* w2t; cudaGetSymbolAddress((void**)&w2t, g_w2t);

    const int N4 = NE * DFF * DM / 4;
    const int CVT_GRID = (N4 + 255) / 256;

    cudaStream_t s2 = 0;
    cudaEvent_t evA = 0, evB = 0, evC = 0;
    bool ok =
        cudaStreamCreateWithFlags(&s2, cudaStreamNonBlocking) == cudaSuccess &&
        cudaEventCreateWithFlags(&evA, cudaEventDisableTiming) == cudaSuccess &&
        cudaEventCreateWithFlags(&evB, cudaEventDisableTiming) == cudaSuccess &&
        cudaEventCreateWithFlags(&evC, cudaEventDisableTiming) == cudaSuccess;
    // objects intentionally leaked: destroying them during active capture is illegal,
    // and kernel_launch runs only a handful of times.

    if (ok) {
        cudaEventRecord(evA, 0);
        cudaStreamWaitEvent(s2, evA, 0);

        cvt_kernel<<<CVT_GRID, 256, 0, s2>>>((const float4*)w1, (uint2*)w1t, N4);
        cvt_kernel<<<CVT_GRID, 256, 0, s2>>>((const float4*)w3, (uint2*)w3t, N4);
        cudaEventRecord(evB, s2);
        cvt_kernel<<<CVT_GRID, 256, 0, s2>>>((const float4*)w2, (uint2*)w2t, N4);
        cudaEventRecord(evC, s2);

        router_kernel<<<N_TOK / 8, 256>>>(x, gw);
        scan_kernel<<<2, 256>>>();
        gather_kernel<<<N_TOK * TOPK, 256>>>(x);

        cudaStreamWaitEvent(0, evB, 0);
        dim3 g1(DFF / 128, CAP / 128, TOPK * NE);
        gemm13_mma<<<g1, 256, SMEM>>>(w1t, w3t);

        cudaStreamWaitEvent(0, evC, 0);
        dim3 g2(DM / 256, CAP / 128, TOPK * NE);
        gemm2_mma<<<g2, 256, SMEM>>>(w2t);

        scatter_kernel<<<N_TOK, 256>>>(out);
        aux_kernel<<<1, 256>>>(out, out_size);
    } else {
        cvt_kernel<<<CVT_GRID, 256>>>((const float4*)w1, (uint2*)w1t, N4);
        cvt_kernel<<<CVT_GRID, 256>>>((const float4*)w3, (uint2*)w3t, N4);
        cvt_kernel<<<CVT_GRID, 256>>>((const float4*)w2, (uint2*)w2t, N4);
        router_kernel<<<N_TOK / 8, 256>>>(x, gw);
        scan_kernel<<<2, 256>>>();
        gather_kernel<<<N_TOK * TOPK, 256>>>(x);
        dim3 g1(DFF / 128, CAP / 128, TOPK * NE);
        gemm13_mma<<<g1, 256, SMEM>>>(w1t, w3t);
        dim3 g2(DM / 256, CAP / 128, TOPK * NE);
        gemm2_mma<<<g2, 256, SMEM>>>(w2t);
        scatter_kernel<<<N_TOK, 256>>>(out);
        aux_kernel<<<1, 256>>>(out, out_size);
    }
}